// round 7
// baseline (speedup 1.0000x reference)
#include <cuda_runtime.h>

#define N_CELL 200000
#define N_WELL 512
#define E_CC   1600000
#define E_CW   65536
#define H      64
#define NEG_SLOPE 0.2f

// ---------------- scratch (static device arrays; no allocation) ----------------
__device__ float g_h[N_CELL * H];
__device__ float g_hs[N_CELL * H];
__device__ float g_num[N_CELL * H];
__device__ float g_as[N_CELL];
__device__ float g_ad[N_CELL];
__device__ float g_s[N_CELL];
__device__ float g_e[E_CC];
__device__ float g_adw[N_WELL];
__device__ float g_sw[N_WELL];
__device__ float g_numw[N_WELL * H];
__device__ float g_ew[E_CW];
__device__ float g_k1[3], g_k0[3];
__device__ int g_cc64, g_cw64;        // 1 if index arrays are int64

// ---------------- index width detection + indexed load ----------------
__global__ void detect_idx64(const void* cc, const void* cw) {
    if (threadIdx.x == 0) {
        const long long* q = (const long long*)cc;
        int ok = 1;
        for (int i = 0; i < 64; i++) {
            long long v = q[(long long)i * 25000];      // spans [0, 1.6M)
            if (v < 0 || v >= N_CELL) { ok = 0; break; }
        }
        g_cc64 = ok;
        const long long* r = (const long long*)cw;
        ok = 1;
        for (int i = 0; i < 64; i++) {
            long long v = r[(long long)i * 1000];       // spans [0, 64K)
            if (v < 0 || v >= N_CELL) { ok = 0; break; }
        }
        g_cw64 = ok;
    }
}

__device__ __forceinline__ int ld_idx(const void* p, long long i, int is64) {
    return is64 ? (int)((const long long*)p)[i] : ((const int*)p)[i];
}

// ---------------- k1/k0: (W_edge @ lin_edge[l]) . att_e[l] ----------------
__global__ void compute_k(const float* __restrict__ W_edge,
                          const float* __restrict__ b_edge,
                          const float* __restrict__ lin_edge,
                          const float* __restrict__ att_e) {
    int l = blockIdx.x;
    int i = threadIdx.x;
    const float* L = lin_edge + l * H * H;
    const float* A = att_e + l * H;
    float r = 0.f;
    for (int j = 0; j < H; j++) r += L[i * H + j] * A[j];
    __shared__ float s1[H], s0[H];
    s1[i] = W_edge[i] * r;
    s0[i] = b_edge[i] * r;
    __syncthreads();
    if (i == 0) {
        float k1 = 0.f, k0 = 0.f;
        for (int j = 0; j < H; j++) { k1 += s1[j]; k0 += s0[j]; }
        g_k1[l] = k1; g_k0[l] = k0;
    }
}

// ---------------- cell embedding ----------------
__global__ void embed_cells(const float* __restrict__ x,
                            const float* __restrict__ W,
                            const float* __restrict__ b) {
    int idx = blockIdx.x * blockDim.x + threadIdx.x;
    if (idx >= N_CELL * H) return;
    int r = idx >> 6, c = idx & 63;
    float acc = b[c];
    for (int i = 0; i < 12; i++) acc += x[r * 12 + i] * W[i * H + c];
    g_h[idx] = acc;
}

// ---------------- GEMM: g_hs = g_h @ W ----------------
__global__ void gemm_cells(const float* __restrict__ W) {
    int idx = blockIdx.x * blockDim.x + threadIdx.x;
    if (idx >= N_CELL * H) return;
    int r = idx >> 6, c = idx & 63;
    const float* a = g_h + (size_t)r * H;
    float acc = 0.f;
    #pragma unroll
    for (int k = 0; k < H; k++) acc += a[k] * W[k * H + c];
    g_hs[idx] = acc;
}

// ---------------- attention dots ----------------
__global__ void att_dots(const float* __restrict__ atts,
                         const float* __restrict__ attd) {
    int gw = (blockIdx.x * blockDim.x + threadIdx.x) >> 5;
    int lane = threadIdx.x & 31;
    if (gw >= N_CELL) return;
    const float* row = g_hs + (size_t)gw * H;
    float s = row[lane] * atts[lane] + row[lane + 32] * atts[lane + 32];
    float d = row[lane] * attd[lane] + row[lane + 32] * attd[lane + 32];
    #pragma unroll
    for (int off = 16; off; off >>= 1) {
        s += __shfl_xor_sync(0xffffffffu, s, off);
        d += __shfl_xor_sync(0xffffffffu, d, off);
    }
    if (lane == 0) { g_as[gw] = s; g_ad[gw] = d; }
}

// ---------------- zeroing ----------------
__global__ void zero_cell() {
    int t = blockIdx.x * blockDim.x + threadIdx.x;
    float4 z = make_float4(0.f, 0.f, 0.f, 0.f);
    if (t < N_CELL * H / 4) reinterpret_cast<float4*>(g_num)[t] = z;
    if (t < N_CELL / 4)     reinterpret_cast<float4*>(g_s)[t]   = z;
}
__global__ void zero_well() {
    int t = blockIdx.x * blockDim.x + threadIdx.x;
    float4 z = make_float4(0.f, 0.f, 0.f, 0.f);
    if (t < N_WELL * H / 4) reinterpret_cast<float4*>(g_numw)[t] = z;
    if (t < N_WELL / 4)     reinterpret_cast<float4*>(g_sw)[t]   = z;
}

// ---------------- cell edge pass A: e = exp(leaky(alpha)), s[d] += e ----------------
__global__ void edge_pass_a(const void* __restrict__ ei,
                            const float* __restrict__ attr, int l) {
    int e = blockIdx.x * blockDim.x + threadIdx.x;
    if (e >= E_CC) return;
    int is64 = g_cc64;
    int s = ld_idx(ei, e, is64);
    int d = ld_idx(ei, (long long)E_CC + e, is64);
    float al = g_as[s] + g_ad[d] + g_k1[l] * attr[e] + g_k0[l];
    al = al > 0.f ? al : NEG_SLOPE * al;
    float ex = expf(al);
    g_e[e] = ex;
    atomicAdd(&g_s[d], ex);
}

// ---------------- cell edge pass B: num[d] += hs[s] * (e / s[d])  (normalized here, ONCE) ----------------
__global__ void edge_pass_b(const void* __restrict__ ei) {
    int t = blockIdx.x * blockDim.x + threadIdx.x;
    int e = t >> 4, sub = t & 15;
    if (e >= E_CC) return;
    int is64 = g_cc64;
    int s = ld_idx(ei, e, is64);
    int d = ld_idx(ei, (long long)E_CC + e, is64);
    float w = g_e[e] / g_s[d];
    float4 v = *reinterpret_cast<const float4*>(&g_hs[(size_t)s * H + sub * 4]);
    float* o = &g_num[(size_t)d * H + sub * 4];
    atomicAdd(o + 0, v.x * w);
    atomicAdd(o + 1, v.y * w);
    atomicAdd(o + 2, v.z * w);
    atomicAdd(o + 3, v.w * w);
}

// ---------------- finalize: h = relu(num + bias)   [num already normalized] ----------------
__global__ void finalize_cells(const float* __restrict__ bias) {
    int idx = blockIdx.x * blockDim.x + threadIdx.x;
    if (idx >= N_CELL * H) return;
    int c = idx & 63;
    g_h[idx] = fmaxf(g_num[idx] + bias[c], 0.f);
}

// ---------------- well prep ----------------
__global__ void well_prep(const float* __restrict__ well_x,
                          const float* __restrict__ Ww,
                          const float* __restrict__ bw,
                          const float* __restrict__ wc_lin,
                          const float* __restrict__ attd) {
    int r = blockIdx.x;
    int c = threadIdx.x;
    __shared__ float hw[64];
    __shared__ float red[64];
    float acc = bw[c];
    for (int i = 0; i < 8; i++) acc += well_x[r * 8 + i] * Ww[i * H + c];
    hw[c] = acc;
    __syncthreads();
    float hd = 0.f;
    for (int k = 0; k < H; k++) hd += hw[k] * wc_lin[k * H + c];
    red[c] = hd * attd[c];
    __syncthreads();
    for (int off = 32; off > 0; off >>= 1) {
        if (c < off) red[c] += red[c + off];
        __syncthreads();
    }
    if (c == 0) g_adw[r] = red[0];
}

// ---------------- well edge passes ----------------
__global__ void well_pass_a(const void* __restrict__ ei) {
    int e = blockIdx.x * blockDim.x + threadIdx.x;
    if (e >= E_CW) return;
    int is64 = g_cw64;
    int s = ld_idx(ei, e, is64);
    int d = ld_idx(ei, (long long)E_CW + e, is64);
    float al = g_as[s] + g_adw[d];
    al = al > 0.f ? al : NEG_SLOPE * al;
    float ex = expf(al);
    g_ew[e] = ex;
    atomicAdd(&g_sw[d], ex);
}

__global__ void well_pass_b(const void* __restrict__ ei) {
    int t = blockIdx.x * blockDim.x + threadIdx.x;
    int e = t >> 4, sub = t & 15;
    if (e >= E_CW) return;
    int is64 = g_cw64;
    int s = ld_idx(ei, e, is64);
    int d = ld_idx(ei, (long long)E_CW + e, is64);
    float w = g_ew[e] / g_sw[d];
    float4 v = *reinterpret_cast<const float4*>(&g_hs[(size_t)s * H + sub * 4]);
    float* o = &g_numw[(size_t)d * H + sub * 4];
    atomicAdd(o + 0, v.x * w);
    atomicAdd(o + 1, v.y * w);
    atomicAdd(o + 2, v.z * w);
    atomicAdd(o + 3, v.w * w);
}

// ---------------- well finalize + MLP  [numw already normalized] ----------------
__global__ void well_finalize(const float* __restrict__ wc_bias,
                              const float* __restrict__ W1,
                              const float* __restrict__ b1,
                              const float* __restrict__ W2,
                              const float* __restrict__ b2,
                              float* __restrict__ out) {
    int r = blockIdx.x;
    int c = threadIdx.x;
    __shared__ float hwell[64];
    __shared__ float t1[64];
    hwell[c] = g_numw[r * H + c] + wc_bias[c];   // NO relu on well GAT output
    __syncthreads();
    float a = b1[c];
    for (int k = 0; k < H; k++) a += hwell[k] * W1[k * H + c];
    t1[c] = fmaxf(a, 0.f);
    __syncthreads();
    for (int o = c; o < 75; o += 64) {
        float acc = b2[o];
        for (int k = 0; k < H; k++) acc += t1[k] * W2[k * 75 + o];
        out[r * 75 + o] = acc;
    }
}

// ---------------- launcher ----------------
extern "C" void kernel_launch(void* const* d_in, const int* in_sizes, int n_in,
                              void* d_out, int out_size) {
    // --- gather: ints by size; floats by size with ambiguity groups ---
    const void* cc_idx = nullptr;
    const void* cw_idx = nullptr;
    const float *cell_x = nullptr, *attr = nullptr, *W_cell_emb = nullptr,
                *W_well_emb = nullptr, *mlp_W2 = nullptr, *mlp_b2 = nullptr;
    const float* a12288[2] = {nullptr, nullptr};
    const float* a4096[3]  = {nullptr, nullptr, nullptr};
    const float* a192[4]   = {nullptr, nullptr, nullptr, nullptr};
    const float* a64[8]    = {nullptr, nullptr, nullptr, nullptr,
                              nullptr, nullptr, nullptr, nullptr};
    int n12288 = 0, n4096 = 0, n192 = 0, n64 = 0;
    int fsz[40]; int nf = 0;

    for (int i = 0; i < n_in; i++) {
        int sz = in_sizes[i];
        const float* p = (const float*)d_in[i];
        switch (sz) {
            case 2 * E_CC: cc_idx = d_in[i]; continue;
            case 2 * E_CW: cw_idx = d_in[i]; continue;
            case 2400000:  cell_x = p; break;
            case 1600000:  attr = p; break;
            case 768:      W_cell_emb = p; break;
            case 512:      W_well_emb = p; break;
            case 4800:     mlp_W2 = p; break;
            case 75:       mlp_b2 = p; break;
            case 12288:    if (n12288 < 2) a12288[n12288++] = p; break;
            case 4096:     if (n4096 < 3)  a4096[n4096++]   = p; break;
            case 192:      if (n192 < 4)   a192[n192++]     = p; break;
            case 64:       if (n64 < 8)    a64[n64++]       = p; break;
            default: break;
        }
        if (nf < 40) fsz[nf++] = sz;
    }

    // --- detect float ordering from the FLOAT size sequence ---
    int ord = 0;
    if (nf > 0 && fsz[0] == 768) ord = 1;
    else if (nf > 3 && fsz[0] == 64 && fsz[3] == 1600000) ord = 2;

    const float* conv_lin      = a12288[0];
    const float* conv_lin_edge = a12288[1];

    const float *conv_att_src, *conv_att_dst, *conv_att_edge, *conv_bias;
    if (ord == 0) { conv_att_src = a192[0]; conv_att_dst = a192[1];
                    conv_att_edge = a192[2]; conv_bias = a192[3]; }
    else          { conv_att_dst = a192[0]; conv_att_edge = a192[1];
                    conv_att_src = a192[2]; conv_bias = a192[3]; }

    const float *well_x, *wc_lin, *mlp_W1;
    if (ord == 0) { well_x = a4096[0]; wc_lin = a4096[1]; mlp_W1 = a4096[2]; }
    else          { mlp_W1 = a4096[0]; wc_lin = a4096[1]; well_x = a4096[2]; }

    const float *b_cell_emb, *b_well_emb, *W_edge_emb, *b_edge_emb,
                *wc_att_src, *wc_att_dst, *wc_bias, *mlp_b1;
    if (ord == 0) {
        b_cell_emb = a64[0]; b_well_emb = a64[1]; W_edge_emb = a64[2];
        b_edge_emb = a64[3]; wc_att_src = a64[4]; wc_att_dst = a64[5];
        wc_bias = a64[6]; mlp_b1 = a64[7];
    } else if (ord == 1) {
        W_edge_emb = a64[0]; b_cell_emb = a64[1]; b_edge_emb = a64[2];
        b_well_emb = a64[3]; mlp_b1 = a64[4]; wc_att_dst = a64[5];
        wc_att_src = a64[6]; wc_bias = a64[7];
    } else {
        b_cell_emb = a64[0]; b_edge_emb = a64[1]; b_well_emb = a64[2];
        mlp_b1 = a64[3]; W_edge_emb = a64[4]; wc_att_dst = a64[5];
        wc_att_src = a64[6]; wc_bias = a64[7];
    }

    const int NB_NH = (N_CELL * H + 255) / 256;

    detect_idx64<<<1, 32>>>(cc_idx, cw_idx);
    compute_k<<<3, 64>>>(W_edge_emb, b_edge_emb, conv_lin_edge, conv_att_edge);
    embed_cells<<<NB_NH, 256>>>(cell_x, W_cell_emb, b_cell_emb);

    for (int l = 0; l < 3; l++) {
        gemm_cells<<<NB_NH, 256>>>(conv_lin + l * H * H);
        att_dots<<<(N_CELL * 32 + 255) / 256, 256>>>(conv_att_src + l * H,
                                                     conv_att_dst + l * H);
        zero_cell<<<(N_CELL * H / 4 + 255) / 256, 256>>>();
        edge_pass_a<<<(E_CC + 255) / 256, 256>>>(cc_idx, attr, l);
        edge_pass_b<<<(E_CC * 16 + 255) / 256, 256>>>(cc_idx);
        finalize_cells<<<NB_NH, 256>>>(conv_bias + l * H);
    }

    // well GAT
    gemm_cells<<<NB_NH, 256>>>(wc_lin);
    att_dots<<<(N_CELL * 32 + 255) / 256, 256>>>(wc_att_src, wc_att_dst);
    well_prep<<<N_WELL, 64>>>(well_x, W_well_emb, b_well_emb, wc_lin, wc_att_dst);
    zero_well<<<(N_WELL * H / 4 + 255) / 256, 256>>>();
    well_pass_a<<<(E_CW + 255) / 256, 256>>>(cw_idx);
    well_pass_b<<<(E_CW * 16 + 255) / 256, 256>>>(cw_idx);
    well_finalize<<<N_WELL, 64>>>(wc_bias, mlp_W1, mlp_b1, mlp_W2, mlp_b2,
                                  (float*)d_out);
}

// round 8
// speedup vs baseline: 2.1659x; 2.1659x over previous
#include <cuda_runtime.h>

#define N_CELL 200000
#define N_WELL 512
#define E_CC   1600000
#define E_CW   65536
#define H      64
#define NEG_SLOPE 0.2f

// ---------------- scratch (static device arrays; no allocation) ----------------
__device__ float g_h[N_CELL * H];
__device__ float g_hs[N_CELL * H];
__device__ float g_num[N_CELL * H];
__device__ float g_as[N_CELL];
__device__ float g_ad[N_CELL];
__device__ float g_s[N_CELL];
__device__ float g_e[E_CC];
__device__ float g_adw[N_WELL];
__device__ float g_sw[N_WELL];
__device__ float g_numw[N_WELL * H];
__device__ float g_ew[E_CW];
__device__ float g_k1[3], g_k0[3];
__device__ int g_cc64, g_cw64;        // 1 if index arrays are int64

// ---------------- index width detection + indexed load ----------------
__global__ void detect_idx64(const void* cc, const void* cw) {
    if (threadIdx.x == 0) {
        const long long* q = (const long long*)cc;
        int ok = 1;
        for (int i = 0; i < 64; i++) {
            long long v = q[(long long)i * 25000];
            if (v < 0 || v >= N_CELL) { ok = 0; break; }
        }
        g_cc64 = ok;
        const long long* r = (const long long*)cw;
        ok = 1;
        for (int i = 0; i < 64; i++) {
            long long v = r[(long long)i * 1000];
            if (v < 0 || v >= N_CELL) { ok = 0; break; }
        }
        g_cw64 = ok;
    }
}

__device__ __forceinline__ int ld_idx(const void* p, long long i, int is64) {
    return is64 ? (int)((const long long*)p)[i] : ((const int*)p)[i];
}

// vector atomic helper (RED.E.ADD.F32x4 on sm_90+)
__device__ __forceinline__ void atomic_add4(float* o, float4 v) {
#if defined(__CUDA_ARCH__) && (__CUDA_ARCH__ >= 900)
    atomicAdd(reinterpret_cast<float4*>(o), v);
#else
    atomicAdd(o + 0, v.x); atomicAdd(o + 1, v.y);
    atomicAdd(o + 2, v.z); atomicAdd(o + 3, v.w);
#endif
}

// ---------------- k1/k0: (W_edge @ lin_edge[l]) . att_e[l] ----------------
__global__ void compute_k(const float* __restrict__ W_edge,
                          const float* __restrict__ b_edge,
                          const float* __restrict__ lin_edge,
                          const float* __restrict__ att_e) {
    int l = blockIdx.x;
    int i = threadIdx.x;
    const float* L = lin_edge + l * H * H;
    const float* A = att_e + l * H;
    float r = 0.f;
    for (int j = 0; j < H; j++) r += L[i * H + j] * A[j];
    __shared__ float s1[H], s0[H];
    s1[i] = W_edge[i] * r;
    s0[i] = b_edge[i] * r;
    __syncthreads();
    if (i == 0) {
        float k1 = 0.f, k0 = 0.f;
        for (int j = 0; j < H; j++) { k1 += s1[j]; k0 += s0[j]; }
        g_k1[l] = k1; g_k0[l] = k0;
    }
}

// ---------------- cell embedding ----------------
__global__ void embed_cells(const float* __restrict__ x,
                            const float* __restrict__ W,
                            const float* __restrict__ b) {
    int idx = blockIdx.x * blockDim.x + threadIdx.x;
    if (idx >= N_CELL * H) return;
    int r = idx >> 6, c = idx & 63;
    float acc = b[c];
    for (int i = 0; i < 12; i++) acc += x[r * 12 + i] * W[i * H + c];
    g_h[idx] = acc;
}

// ---------------- fused GEMM ----------------
// Computes hs = f(in) @ W where f = identity (transform=0, in=g_h) or
// relu(g_num + bias) (transform=1, finalize of previous layer fused).
// Epilogue: g_as/g_ad attention dots, and zeroing of g_num/g_s for the
// upcoming edge passes (disjoint per block; this kernel always precedes them).
__global__ __launch_bounds__(256) void gemm_fused(
    const float* __restrict__ W,
    const float* __restrict__ atts,
    const float* __restrict__ attd,
    const float* __restrict__ bias,
    int transform)
{
    __shared__ float shH[64][65];
    __shared__ float shL[64][64];
    __shared__ float shB[64];
    __shared__ float redS[64], redD[64];

    int tid = threadIdx.x;
    int r0 = blockIdx.x * 64;

    if (tid < 64) {
        shB[tid] = transform ? bias[tid] : 0.f;
        redS[tid] = 0.f; redD[tid] = 0.f;
    }
    __syncthreads();

    // W tile (float4 loads)
    const float4* W4 = reinterpret_cast<const float4*>(W);
    for (int i = tid; i < 1024; i += 256) {
        float4 v = W4[i];
        int k = i >> 4, c = (i & 15) << 2;
        shL[k][c] = v.x; shL[k][c + 1] = v.y; shL[k][c + 2] = v.z; shL[k][c + 3] = v.w;
    }
    // input tile (float4 loads, fused finalize)
    const float4* src4 = reinterpret_cast<const float4*>(transform ? g_num : g_h);
    for (int i = tid; i < 1024; i += 256) {
        float4 v = src4[(size_t)r0 * 16 + i];
        int rr = i >> 4, c = (i & 15) << 2;
        if (transform) {
            v.x = fmaxf(v.x + shB[c], 0.f);
            v.y = fmaxf(v.y + shB[c + 1], 0.f);
            v.z = fmaxf(v.z + shB[c + 2], 0.f);
            v.w = fmaxf(v.w + shB[c + 3], 0.f);
        }
        shH[rr][c] = v.x; shH[rr][c + 1] = v.y; shH[rr][c + 2] = v.z; shH[rr][c + 3] = v.w;
    }
    __syncthreads();

    int row = tid & 63;
    int cg = (tid >> 6) << 4;
    float acc[16];
    #pragma unroll
    for (int j = 0; j < 16; j++) acc[j] = 0.f;

    #pragma unroll 8
    for (int k = 0; k < H; k++) {
        float a = shH[row][k];
        #pragma unroll
        for (int j = 0; j < 16; j++) acc[j] += a * shL[k][cg + j];
    }

    // fused attention dots
    float ps = 0.f, pd = 0.f;
    #pragma unroll
    for (int j = 0; j < 16; j++) {
        ps += acc[j] * atts[cg + j];
        pd += acc[j] * attd[cg + j];
    }
    atomicAdd(&redS[row], ps);
    atomicAdd(&redD[row], pd);

    // store hs + zero g_num slice for upcoming scatter
    float4* dst = reinterpret_cast<float4*>(&g_hs[(size_t)(r0 + row) * H + cg]);
    float4* znum = reinterpret_cast<float4*>(&g_num[(size_t)(r0 + row) * H + cg]);
    float4 z = make_float4(0.f, 0.f, 0.f, 0.f);
    dst[0] = make_float4(acc[0], acc[1], acc[2], acc[3]);   znum[0] = z;
    dst[1] = make_float4(acc[4], acc[5], acc[6], acc[7]);   znum[1] = z;
    dst[2] = make_float4(acc[8], acc[9], acc[10], acc[11]); znum[2] = z;
    dst[3] = make_float4(acc[12], acc[13], acc[14], acc[15]); znum[3] = z;

    __syncthreads();
    if (tid < 64) {
        g_as[r0 + tid] = redS[tid];
        g_ad[r0 + tid] = redD[tid];
        g_s[r0 + tid] = 0.f;
    }
}

// ---------------- cell edge pass A: e = exp(leaky(alpha)), s[d] += e ----------------
__global__ void edge_pass_a(const void* __restrict__ ei,
                            const float* __restrict__ attr, int l) {
    int e = blockIdx.x * blockDim.x + threadIdx.x;
    if (e >= E_CC) return;
    int is64 = g_cc64;
    int s = ld_idx(ei, e, is64);
    int d = ld_idx(ei, (long long)E_CC + e, is64);
    float al = g_as[s] + g_ad[d] + g_k1[l] * attr[e] + g_k0[l];
    al = al > 0.f ? al : NEG_SLOPE * al;
    float ex = __expf(al);
    g_e[e] = ex;
    atomicAdd(&g_s[d], ex);
}

// ---------------- reciprocal of softmax denominators ----------------
__global__ void recip_s_cell() {
    int i = blockIdx.x * blockDim.x + threadIdx.x;
    if (i < N_CELL) g_s[i] = 1.f / g_s[i];
}
__global__ void recip_s_well() {
    int i = blockIdx.x * blockDim.x + threadIdx.x;
    if (i < N_WELL) g_sw[i] = 1.f / g_sw[i];
}

// ---------------- cell edge pass B: num[d] += hs[s] * (e * sinv[d]) ----------------
__global__ void edge_pass_b(const void* __restrict__ ei) {
    int t = blockIdx.x * blockDim.x + threadIdx.x;
    int e = t >> 4, sub = t & 15;
    if (e >= E_CC) return;
    int is64 = g_cc64;
    int s = ld_idx(ei, e, is64);
    int d = ld_idx(ei, (long long)E_CC + e, is64);
    float w = g_e[e] * g_s[d];             // g_s holds 1/s
    float4 v = *reinterpret_cast<const float4*>(&g_hs[(size_t)s * H + sub * 4]);
    atomic_add4(&g_num[(size_t)d * H + sub * 4],
                make_float4(v.x * w, v.y * w, v.z * w, v.w * w));
}

// ---------------- well prep ----------------
__global__ void well_prep(const float* __restrict__ well_x,
                          const float* __restrict__ Ww,
                          const float* __restrict__ bw,
                          const float* __restrict__ wc_lin,
                          const float* __restrict__ attd) {
    int r = blockIdx.x;
    int c = threadIdx.x;
    __shared__ float hw[64];
    __shared__ float red[64];
    float acc = bw[c];
    for (int i = 0; i < 8; i++) acc += well_x[r * 8 + i] * Ww[i * H + c];
    hw[c] = acc;
    __syncthreads();
    float hd = 0.f;
    for (int k = 0; k < H; k++) hd += hw[k] * wc_lin[k * H + c];
    red[c] = hd * attd[c];
    __syncthreads();
    for (int off = 32; off > 0; off >>= 1) {
        if (c < off) red[c] += red[c + off];
        __syncthreads();
    }
    if (c == 0) g_adw[r] = red[0];
}

// ---------------- zero well accumulators ----------------
__global__ void zero_well() {
    int t = blockIdx.x * blockDim.x + threadIdx.x;
    float4 z = make_float4(0.f, 0.f, 0.f, 0.f);
    if (t < N_WELL * H / 4) reinterpret_cast<float4*>(g_numw)[t] = z;
    if (t < N_WELL / 4)     reinterpret_cast<float4*>(g_sw)[t]   = z;
}

// ---------------- well edge passes ----------------
__global__ void well_pass_a(const void* __restrict__ ei) {
    int e = blockIdx.x * blockDim.x + threadIdx.x;
    if (e >= E_CW) return;
    int is64 = g_cw64;
    int s = ld_idx(ei, e, is64);
    int d = ld_idx(ei, (long long)E_CW + e, is64);
    float al = g_as[s] + g_adw[d];
    al = al > 0.f ? al : NEG_SLOPE * al;
    float ex = __expf(al);
    g_ew[e] = ex;
    atomicAdd(&g_sw[d], ex);
}

__global__ void well_pass_b(const void* __restrict__ ei) {
    int t = blockIdx.x * blockDim.x + threadIdx.x;
    int e = t >> 4, sub = t & 15;
    if (e >= E_CW) return;
    int is64 = g_cw64;
    int s = ld_idx(ei, e, is64);
    int d = ld_idx(ei, (long long)E_CW + e, is64);
    float w = g_ew[e] * g_sw[d];           // g_sw holds 1/s
    float4 v = *reinterpret_cast<const float4*>(&g_hs[(size_t)s * H + sub * 4]);
    atomic_add4(&g_numw[(size_t)d * H + sub * 4],
                make_float4(v.x * w, v.y * w, v.z * w, v.w * w));
}

// ---------------- well finalize + MLP ----------------
__global__ void well_finalize(const float* __restrict__ wc_bias,
                              const float* __restrict__ W1,
                              const float* __restrict__ b1,
                              const float* __restrict__ W2,
                              const float* __restrict__ b2,
                              float* __restrict__ out) {
    int r = blockIdx.x;
    int c = threadIdx.x;
    __shared__ float hwell[64];
    __shared__ float t1[64];
    hwell[c] = g_numw[r * H + c] + wc_bias[c];   // NO relu on well GAT output
    __syncthreads();
    float a = b1[c];
    for (int k = 0; k < H; k++) a += hwell[k] * W1[k * H + c];
    t1[c] = fmaxf(a, 0.f);
    __syncthreads();
    for (int o = c; o < 75; o += 64) {
        float acc = b2[o];
        for (int k = 0; k < H; k++) acc += t1[k] * W2[k * 75 + o];
        out[r * 75 + o] = acc;
    }
}

// ---------------- launcher ----------------
extern "C" void kernel_launch(void* const* d_in, const int* in_sizes, int n_in,
                              void* d_out, int out_size) {
    const void* cc_idx = nullptr;
    const void* cw_idx = nullptr;
    const float *cell_x = nullptr, *attr = nullptr, *W_cell_emb = nullptr,
                *W_well_emb = nullptr, *mlp_W2 = nullptr, *mlp_b2 = nullptr;
    const float* a12288[2] = {nullptr, nullptr};
    const float* a4096[3]  = {nullptr, nullptr, nullptr};
    const float* a192[4]   = {nullptr, nullptr, nullptr, nullptr};
    const float* a64[8]    = {nullptr, nullptr, nullptr, nullptr,
                              nullptr, nullptr, nullptr, nullptr};
    int n12288 = 0, n4096 = 0, n192 = 0, n64 = 0;
    int fsz[40]; int nf = 0;

    for (int i = 0; i < n_in; i++) {
        int sz = in_sizes[i];
        const float* p = (const float*)d_in[i];
        switch (sz) {
            case 2 * E_CC: cc_idx = d_in[i]; continue;
            case 2 * E_CW: cw_idx = d_in[i]; continue;
            case 2400000:  cell_x = p; break;
            case 1600000:  attr = p; break;
            case 768:      W_cell_emb = p; break;
            case 512:      W_well_emb = p; break;
            case 4800:     mlp_W2 = p; break;
            case 75:       mlp_b2 = p; break;
            case 12288:    if (n12288 < 2) a12288[n12288++] = p; break;
            case 4096:     if (n4096 < 3)  a4096[n4096++]   = p; break;
            case 192:      if (n192 < 4)   a192[n192++]     = p; break;
            case 64:       if (n64 < 8)    a64[n64++]       = p; break;
            default: break;
        }
        if (nf < 40) fsz[nf++] = sz;
    }

    int ord = 0;
    if (nf > 0 && fsz[0] == 768) ord = 1;
    else if (nf > 3 && fsz[0] == 64 && fsz[3] == 1600000) ord = 2;

    const float* conv_lin      = a12288[0];
    const float* conv_lin_edge = a12288[1];

    const float *conv_att_src, *conv_att_dst, *conv_att_edge, *conv_bias;
    if (ord == 0) { conv_att_src = a192[0]; conv_att_dst = a192[1];
                    conv_att_edge = a192[2]; conv_bias = a192[3]; }
    else          { conv_att_dst = a192[0]; conv_att_edge = a192[1];
                    conv_att_src = a192[2]; conv_bias = a192[3]; }

    const float *well_x, *wc_lin, *mlp_W1;
    if (ord == 0) { well_x = a4096[0]; wc_lin = a4096[1]; mlp_W1 = a4096[2]; }
    else          { mlp_W1 = a4096[0]; wc_lin = a4096[1]; well_x = a4096[2]; }

    const float *b_cell_emb, *b_well_emb, *W_edge_emb, *b_edge_emb,
                *wc_att_src, *wc_att_dst, *wc_bias, *mlp_b1;
    if (ord == 0) {
        b_cell_emb = a64[0]; b_well_emb = a64[1]; W_edge_emb = a64[2];
        b_edge_emb = a64[3]; wc_att_src = a64[4]; wc_att_dst = a64[5];
        wc_bias = a64[6]; mlp_b1 = a64[7];
    } else if (ord == 1) {
        W_edge_emb = a64[0]; b_cell_emb = a64[1]; b_edge_emb = a64[2];
        b_well_emb = a64[3]; mlp_b1 = a64[4]; wc_att_dst = a64[5];
        wc_att_src = a64[6]; wc_bias = a64[7];
    } else {
        b_cell_emb = a64[0]; b_edge_emb = a64[1]; b_well_emb = a64[2];
        mlp_b1 = a64[3]; W_edge_emb = a64[4]; wc_att_dst = a64[5];
        wc_att_src = a64[6]; wc_bias = a64[7];
    }

    detect_idx64<<<1, 32>>>(cc_idx, cw_idx);
    compute_k<<<3, 64>>>(W_edge_emb, b_edge_emb, conv_lin_edge, conv_att_edge);
    embed_cells<<<(N_CELL * H + 255) / 256, 256>>>(cell_x, W_cell_emb, b_cell_emb);

    for (int l = 0; l < 3; l++) {
        gemm_fused<<<N_CELL / 64, 256>>>(
            conv_lin + l * H * H,
            conv_att_src + l * H,
            conv_att_dst + l * H,
            l == 0 ? conv_bias : conv_bias + (l - 1) * H,
            l == 0 ? 0 : 1);
        edge_pass_a<<<(E_CC + 255) / 256, 256>>>(cc_idx, attr, l);
        recip_s_cell<<<(N_CELL + 255) / 256, 256>>>();
        edge_pass_b<<<(E_CC * 16 + 255) / 256, 256>>>(cc_idx);
    }

    // well GAT (finalize of layer 2 fused into this gemm's load)
    gemm_fused<<<N_CELL / 64, 256>>>(wc_lin, wc_att_src, wc_att_dst,
                                     conv_bias + 2 * H, 1);
    well_prep<<<N_WELL, 64>>>(well_x, W_well_emb, b_well_emb, wc_lin, wc_att_dst);
    zero_well<<<(N_WELL * H / 4 + 255) / 256, 256>>>();
    well_pass_a<<<(E_CW + 255) / 256, 256>>>(cw_idx);
    recip_s_well<<<(N_WELL + 255) / 256, 256>>>();
    well_pass_b<<<(E_CW * 16 + 255) / 256, 256>>>(cw_idx);
    well_finalize<<<N_WELL, 64>>>(wc_bias, mlp_W1, mlp_b1, mlp_W2, mlp_b2,
                                  (float*)d_out);
}

// round 9
// speedup vs baseline: 2.8729x; 1.3264x over previous
#include <cuda_runtime.h>

#define N_CELL 200000
#define N_WELL 512
#define E_CC   1600000
#define E_CW   65536
#define H      64
#define NEG_SLOPE 0.2f

// ---------------- scratch (static device arrays; no allocation) ----------------
__device__ float g_hs[N_CELL * H];
__device__ float g_num[N_CELL * H];
__device__ float g_as[N_CELL];
__device__ float g_ad[N_CELL];
__device__ float g_s[N_CELL];          // holds 1/sum per dst
__device__ float g_e[E_CC];            // per-edge exp (CSR order)
__device__ float g_adw[N_WELL];
__device__ float g_sw[N_WELL];
__device__ float g_numw[N_WELL * H];
__device__ float g_ew[E_CW];
__device__ float g_k1[3], g_k0[3];
__device__ float g_W0[12 * H];         // W_cell_emb @ conv_lin[0]
__device__ float g_b0[H];              // b_cell_emb @ conv_lin[0]
__device__ int g_cc64, g_cw64;

// CSR scratch
__device__ int g_off[N_CELL + 1];
__device__ int g_cur[N_CELL];          // degree counts, then cursors
__device__ int g_srcp[E_CC];
__device__ float g_attrp[E_CC];
__device__ int g_bsum[256];
__device__ int g_woff[N_WELL + 1];
__device__ int g_wcur[N_WELL];
__device__ int g_wsrcp[E_CW];

// ---------------- helpers ----------------
__global__ void detect_idx64(const void* cc, const void* cw) {
    if (threadIdx.x == 0) {
        const long long* q = (const long long*)cc;
        int ok = 1;
        for (int i = 0; i < 64; i++) {
            long long v = q[(long long)i * 25000];
            if (v < 0 || v >= N_CELL) { ok = 0; break; }
        }
        g_cc64 = ok;
        const long long* r = (const long long*)cw;
        ok = 1;
        for (int i = 0; i < 64; i++) {
            long long v = r[(long long)i * 1000];
            if (v < 0 || v >= N_CELL) { ok = 0; break; }
        }
        g_cw64 = ok;
    }
}

__device__ __forceinline__ int ld_idx(const void* p, long long i, int is64) {
    return is64 ? (int)((const long long*)p)[i] : ((const int*)p)[i];
}

// ---------------- k1/k0 + layer-0 weight fold ----------------
__global__ void compute_k(const float* __restrict__ W_edge,
                          const float* __restrict__ b_edge,
                          const float* __restrict__ lin_edge,
                          const float* __restrict__ att_e) {
    int l = blockIdx.x;
    int i = threadIdx.x;
    const float* L = lin_edge + l * H * H;
    const float* A = att_e + l * H;
    float r = 0.f;
    for (int j = 0; j < H; j++) r += L[i * H + j] * A[j];
    __shared__ float s1[H], s0[H];
    s1[i] = W_edge[i] * r;
    s0[i] = b_edge[i] * r;
    __syncthreads();
    if (i == 0) {
        float k1 = 0.f, k0 = 0.f;
        for (int j = 0; j < H; j++) { k1 += s1[j]; k0 += s0[j]; }
        g_k1[l] = k1; g_k0[l] = k0;
    }
}

__global__ void prep_W0(const float* __restrict__ Wemb,
                        const float* __restrict__ bemb,
                        const float* __restrict__ lin0) {
    int idx = blockIdx.x * blockDim.x + threadIdx.x;
    if (idx >= 13 * 64) return;
    int i = idx >> 6, c = idx & 63;
    float s = 0.f;
    if (i < 12) {
        for (int k = 0; k < H; k++) s += Wemb[i * H + k] * lin0[k * H + c];
        g_W0[i * H + c] = s;
    } else {
        for (int k = 0; k < H; k++) s += bemb[k] * lin0[k * H + c];
        g_b0[c] = s;
    }
}

// ---------------- CSR build (cells) ----------------
__global__ void zero_deg() {
    int i = blockIdx.x * blockDim.x + threadIdx.x;
    if (i < N_CELL) g_cur[i] = 0;
}
__global__ void hist_cc(const void* __restrict__ ei) {
    int e = blockIdx.x * blockDim.x + threadIdx.x;
    if (e >= E_CC) return;
    int d = ld_idx(ei, (long long)E_CC + e, g_cc64);
    atomicAdd(&g_cur[d], 1);
}
__global__ void scan1() {
    __shared__ int sh[1024];
    int tid = threadIdx.x;
    int gid = blockIdx.x * 1024 + tid;
    int v = (gid < N_CELL) ? g_cur[gid] : 0;
    sh[tid] = v;
    __syncthreads();
    for (int off = 1; off < 1024; off <<= 1) {
        int t = (tid >= off) ? sh[tid - off] : 0;
        __syncthreads();
        sh[tid] += t;
        __syncthreads();
    }
    if (gid < N_CELL) g_off[gid] = sh[tid] - v;     // exclusive within block
    if (tid == 1023) g_bsum[blockIdx.x] = sh[1023]; // block total
}
__global__ void scan2(int nblk) {
    if (threadIdx.x == 0) {
        int acc = 0;
        for (int b = 0; b < nblk; b++) { int t = g_bsum[b]; g_bsum[b] = acc; acc += t; }
        g_off[N_CELL] = E_CC;
    }
}
__global__ void scan3() {
    int gid = blockIdx.x * blockDim.x + threadIdx.x;
    if (gid >= N_CELL) return;
    int o = g_off[gid] + g_bsum[gid >> 10];
    g_off[gid] = o;
    g_cur[gid] = o;
}
__global__ void scatter_cc(const void* __restrict__ ei,
                           const float* __restrict__ attr) {
    int e = blockIdx.x * blockDim.x + threadIdx.x;
    if (e >= E_CC) return;
    int is64 = g_cc64;
    int s = ld_idx(ei, e, is64);
    int d = ld_idx(ei, (long long)E_CC + e, is64);
    int p = atomicAdd(&g_cur[d], 1);
    g_srcp[p] = s;
    g_attrp[p] = attr[e];
}

// ---------------- CSR build (wells) ----------------
__global__ void wzero() {
    int i = blockIdx.x * blockDim.x + threadIdx.x;
    if (i < N_WELL) g_wcur[i] = 0;
}
__global__ void whist(const void* __restrict__ ei) {
    int e = blockIdx.x * blockDim.x + threadIdx.x;
    if (e >= E_CW) return;
    int d = ld_idx(ei, (long long)E_CW + e, g_cw64);
    atomicAdd(&g_wcur[d], 1);
}
__global__ void wscan() {
    __shared__ int sh[512];
    int tid = threadIdx.x;
    int v = g_wcur[tid];
    sh[tid] = v;
    __syncthreads();
    for (int off = 1; off < 512; off <<= 1) {
        int t = (tid >= off) ? sh[tid - off] : 0;
        __syncthreads();
        sh[tid] += t;
        __syncthreads();
    }
    g_woff[tid] = sh[tid] - v;
    g_wcur[tid] = sh[tid] - v;
    if (tid == 0) g_woff[N_WELL] = E_CW;
}
__global__ void wscatter(const void* __restrict__ ei) {
    int e = blockIdx.x * blockDim.x + threadIdx.x;
    if (e >= E_CW) return;
    int is64 = g_cw64;
    int s = ld_idx(ei, e, is64);
    int d = ld_idx(ei, (long long)E_CW + e, is64);
    int p = atomicAdd(&g_wcur[d], 1);
    g_wsrcp[p] = s;
}

// ---------------- GEMM layer 0: hs = cell_x @ W0 + b0, fused att dots ----------------
__global__ __launch_bounds__(256) void gemm12(
    const float* __restrict__ x,
    const float* __restrict__ atts,
    const float* __restrict__ attd)
{
    __shared__ float shX[64][13];
    __shared__ float shW[12][64];
    __shared__ float shB[64];
    int tid = threadIdx.x;
    int r0 = blockIdx.x * 64;

    if (tid < 64) shB[tid] = g_b0[tid];
    for (int i = tid; i < 12 * 64; i += 256) shW[i >> 6][i & 63] = g_W0[i];
    for (int i = tid; i < 64 * 12; i += 256) shX[i / 12][i % 12] = x[(size_t)r0 * 12 + i];
    __syncthreads();

    int rg = tid >> 4, cg = tid & 15;
    int row0 = rg << 2, col0 = cg << 2;
    float acc[4][4];
    #pragma unroll
    for (int xx = 0; xx < 4; xx++)
        #pragma unroll
        for (int j = 0; j < 4; j++) acc[xx][j] = shB[col0 + j];

    #pragma unroll
    for (int k = 0; k < 12; k++) {
        float4 wv = *(const float4*)&shW[k][col0];
        float a0 = shX[row0][k], a1 = shX[row0 + 1][k];
        float a2 = shX[row0 + 2][k], a3 = shX[row0 + 3][k];
        acc[0][0] += a0 * wv.x; acc[0][1] += a0 * wv.y; acc[0][2] += a0 * wv.z; acc[0][3] += a0 * wv.w;
        acc[1][0] += a1 * wv.x; acc[1][1] += a1 * wv.y; acc[1][2] += a1 * wv.z; acc[1][3] += a1 * wv.w;
        acc[2][0] += a2 * wv.x; acc[2][1] += a2 * wv.y; acc[2][2] += a2 * wv.z; acc[2][3] += a2 * wv.w;
        acc[3][0] += a3 * wv.x; acc[3][1] += a3 * wv.y; acc[3][2] += a3 * wv.z; acc[3][3] += a3 * wv.w;
    }

    #pragma unroll
    for (int xx = 0; xx < 4; xx++) {
        float ps = acc[xx][0] * atts[col0] + acc[xx][1] * atts[col0 + 1]
                 + acc[xx][2] * atts[col0 + 2] + acc[xx][3] * atts[col0 + 3];
        float pd = acc[xx][0] * attd[col0] + acc[xx][1] * attd[col0 + 1]
                 + acc[xx][2] * attd[col0 + 2] + acc[xx][3] * attd[col0 + 3];
        #pragma unroll
        for (int off = 8; off; off >>= 1) {
            ps += __shfl_xor_sync(0xffffffffu, ps, off);
            pd += __shfl_xor_sync(0xffffffffu, pd, off);
        }
        if ((tid & 15) == 0) {
            g_as[r0 + row0 + xx] = ps;
            g_ad[r0 + row0 + xx] = pd;
        }
        *(float4*)&g_hs[(size_t)(r0 + row0 + xx) * H + col0] =
            make_float4(acc[xx][0], acc[xx][1], acc[xx][2], acc[xx][3]);
    }
}

// ---------------- GEMM layers 1+: hs = relu(g_num + bias) @ W, fused att dots ----------------
__global__ __launch_bounds__(256) void gemm_fused(
    const float* __restrict__ W,
    const float* __restrict__ atts,
    const float* __restrict__ attd,
    const float* __restrict__ bias)
{
    __shared__ float shH[64][68];
    __shared__ float shW[64][64];
    __shared__ float shB[64];
    int tid = threadIdx.x;
    int r0 = blockIdx.x * 64;

    if (tid < 64) shB[tid] = bias[tid];
    __syncthreads();

    const float4* W4 = (const float4*)W;
    for (int i = tid; i < 1024; i += 256) {
        int k = i >> 4, c = (i & 15) << 2;
        *(float4*)&shW[k][c] = W4[i];
    }
    const float4* src4 = (const float4*)g_num;
    for (int i = tid; i < 1024; i += 256) {
        float4 v = src4[(size_t)r0 * 16 + i];
        int rr = i >> 4, c = (i & 15) << 2;
        v.x = fmaxf(v.x + shB[c], 0.f);
        v.y = fmaxf(v.y + shB[c + 1], 0.f);
        v.z = fmaxf(v.z + shB[c + 2], 0.f);
        v.w = fmaxf(v.w + shB[c + 3], 0.f);
        *(float4*)&shH[rr][c] = v;
    }
    __syncthreads();

    int rg = tid >> 4, cg = tid & 15;
    int row0 = rg << 2, col0 = cg << 2;
    float acc[4][4] = {};

    #pragma unroll 8
    for (int k = 0; k < H; k++) {
        float4 wv = *(const float4*)&shW[k][col0];
        float a0 = shH[row0][k], a1 = shH[row0 + 1][k];
        float a2 = shH[row0 + 2][k], a3 = shH[row0 + 3][k];
        acc[0][0] += a0 * wv.x; acc[0][1] += a0 * wv.y; acc[0][2] += a0 * wv.z; acc[0][3] += a0 * wv.w;
        acc[1][0] += a1 * wv.x; acc[1][1] += a1 * wv.y; acc[1][2] += a1 * wv.z; acc[1][3] += a1 * wv.w;
        acc[2][0] += a2 * wv.x; acc[2][1] += a2 * wv.y; acc[2][2] += a2 * wv.z; acc[2][3] += a2 * wv.w;
        acc[3][0] += a3 * wv.x; acc[3][1] += a3 * wv.y; acc[3][2] += a3 * wv.z; acc[3][3] += a3 * wv.w;
    }

    #pragma unroll
    for (int xx = 0; xx < 4; xx++) {
        float ps = acc[xx][0] * atts[col0] + acc[xx][1] * atts[col0 + 1]
                 + acc[xx][2] * atts[col0 + 2] + acc[xx][3] * atts[col0 + 3];
        float pd = acc[xx][0] * attd[col0] + acc[xx][1] * attd[col0 + 1]
                 + acc[xx][2] * attd[col0 + 2] + acc[xx][3] * attd[col0 + 3];
        #pragma unroll
        for (int off = 8; off; off >>= 1) {
            ps += __shfl_xor_sync(0xffffffffu, ps, off);
            pd += __shfl_xor_sync(0xffffffffu, pd, off);
        }
        if ((tid & 15) == 0) {
            g_as[r0 + row0 + xx] = ps;
            g_ad[r0 + row0 + xx] = pd;
        }
        *(float4*)&g_hs[(size_t)(r0 + row0 + xx) * H + col0] =
            make_float4(acc[xx][0], acc[xx][1], acc[xx][2], acc[xx][3]);
    }
}

// ---------------- CSR edge pass A: per-dst exp + 1/sum (no atomics) ----------------
__global__ void pass_a_csr(int l) {
    int d = blockIdx.x * blockDim.x + threadIdx.x;
    if (d >= N_CELL) return;
    int beg = g_off[d], end = g_off[d + 1];
    float adv = g_ad[d];
    float k1 = g_k1[l], k0 = g_k0[l];
    float s = 0.f;
    for (int j = beg; j < end; j++) {
        float al = g_as[g_srcp[j]] + adv + k1 * g_attrp[j] + k0;
        al = al > 0.f ? al : NEG_SLOPE * al;
        float ex = __expf(al);
        g_e[j] = ex;
        s += ex;
    }
    g_s[d] = 1.f / s;
}

// ---------------- CSR edge pass B: warp-per-dst register aggregation (no atomics) ----------------
__global__ __launch_bounds__(256) void pass_b_csr() {
    int w = (blockIdx.x * blockDim.x + threadIdx.x) >> 5;
    if (w >= N_CELL) return;
    int lane = threadIdx.x & 31;
    int half = lane >> 4, li = lane & 15;
    int beg = g_off[w], end = g_off[w + 1];
    float sinv = g_s[w];
    float4 acc = make_float4(0.f, 0.f, 0.f, 0.f);
    for (int j = beg + half; j < end; j += 2) {
        int s = g_srcp[j];
        float wt = g_e[j] * sinv;
        float4 v = *(const float4*)&g_hs[(size_t)s * H + li * 4];
        acc.x += v.x * wt; acc.y += v.y * wt; acc.z += v.z * wt; acc.w += v.w * wt;
    }
    acc.x += __shfl_down_sync(0xffffffffu, acc.x, 16);
    acc.y += __shfl_down_sync(0xffffffffu, acc.y, 16);
    acc.z += __shfl_down_sync(0xffffffffu, acc.z, 16);
    acc.w += __shfl_down_sync(0xffffffffu, acc.w, 16);
    if (lane < 16) *(float4*)&g_num[(size_t)w * H + li * 4] = acc;
}

// ---------------- well path ----------------
__global__ void well_prep(const float* __restrict__ well_x,
                          const float* __restrict__ Ww,
                          const float* __restrict__ bw,
                          const float* __restrict__ wc_lin,
                          const float* __restrict__ attd) {
    int r = blockIdx.x;
    int c = threadIdx.x;
    __shared__ float hw[64];
    __shared__ float red[64];
    float acc = bw[c];
    for (int i = 0; i < 8; i++) acc += well_x[r * 8 + i] * Ww[i * H + c];
    hw[c] = acc;
    __syncthreads();
    float hd = 0.f;
    for (int k = 0; k < H; k++) hd += hw[k] * wc_lin[k * H + c];
    red[c] = hd * attd[c];
    __syncthreads();
    for (int off = 32; off > 0; off >>= 1) {
        if (c < off) red[c] += red[c + off];
        __syncthreads();
    }
    if (c == 0) g_adw[r] = red[0];
}

__global__ void well_pass_a_csr() {
    int d = blockIdx.x * blockDim.x + threadIdx.x;
    if (d >= N_WELL) return;
    int beg = g_woff[d], end = g_woff[d + 1];
    float adv = g_adw[d];
    float s = 0.f;
    for (int j = beg; j < end; j++) {
        float al = g_as[g_wsrcp[j]] + adv;
        al = al > 0.f ? al : NEG_SLOPE * al;
        float ex = __expf(al);
        g_ew[j] = ex;
        s += ex;
    }
    g_sw[d] = 1.f / s;
}

__global__ __launch_bounds__(256) void well_pass_b_csr() {
    int w = (blockIdx.x * blockDim.x + threadIdx.x) >> 5;
    if (w >= N_WELL) return;
    int lane = threadIdx.x & 31;
    int half = lane >> 4, li = lane & 15;
    int beg = g_woff[w], end = g_woff[w + 1];
    float sinv = g_sw[w];
    float4 acc = make_float4(0.f, 0.f, 0.f, 0.f);
    for (int j = beg + half; j < end; j += 2) {
        int s = g_wsrcp[j];
        float wt = g_ew[j] * sinv;
        float4 v = *(const float4*)&g_hs[(size_t)s * H + li * 4];
        acc.x += v.x * wt; acc.y += v.y * wt; acc.z += v.z * wt; acc.w += v.w * wt;
    }
    acc.x += __shfl_down_sync(0xffffffffu, acc.x, 16);
    acc.y += __shfl_down_sync(0xffffffffu, acc.y, 16);
    acc.z += __shfl_down_sync(0xffffffffu, acc.z, 16);
    acc.w += __shfl_down_sync(0xffffffffu, acc.w, 16);
    if (lane < 16) *(float4*)&g_numw[(size_t)w * H + li * 4] = acc;
}

__global__ void well_finalize(const float* __restrict__ wc_bias,
                              const float* __restrict__ W1,
                              const float* __restrict__ b1,
                              const float* __restrict__ W2,
                              const float* __restrict__ b2,
                              float* __restrict__ out) {
    int r = blockIdx.x;
    int c = threadIdx.x;
    __shared__ float hwell[64];
    __shared__ float t1[64];
    hwell[c] = g_numw[r * H + c] + wc_bias[c];
    __syncthreads();
    float a = b1[c];
    for (int k = 0; k < H; k++) a += hwell[k] * W1[k * H + c];
    t1[c] = fmaxf(a, 0.f);
    __syncthreads();
    for (int o = c; o < 75; o += 64) {
        float acc = b2[o];
        for (int k = 0; k < H; k++) acc += t1[k] * W2[k * 75 + o];
        out[r * 75 + o] = acc;
    }
}

// ---------------- launcher ----------------
extern "C" void kernel_launch(void* const* d_in, const int* in_sizes, int n_in,
                              void* d_out, int out_size) {
    const void* cc_idx = nullptr;
    const void* cw_idx = nullptr;
    const float *cell_x = nullptr, *attr = nullptr, *W_cell_emb = nullptr,
                *W_well_emb = nullptr, *mlp_W2 = nullptr, *mlp_b2 = nullptr;
    const float* a12288[2] = {nullptr, nullptr};
    const float* a4096[3]  = {nullptr, nullptr, nullptr};
    const float* a192[4]   = {nullptr, nullptr, nullptr, nullptr};
    const float* a64[8]    = {nullptr, nullptr, nullptr, nullptr,
                              nullptr, nullptr, nullptr, nullptr};
    int n12288 = 0, n4096 = 0, n192 = 0, n64 = 0;
    int fsz[40]; int nf = 0;

    for (int i = 0; i < n_in; i++) {
        int sz = in_sizes[i];
        const float* p = (const float*)d_in[i];
        switch (sz) {
            case 2 * E_CC: cc_idx = d_in[i]; continue;
            case 2 * E_CW: cw_idx = d_in[i]; continue;
            case 2400000:  cell_x = p; break;
            case 1600000:  attr = p; break;
            case 768:      W_cell_emb = p; break;
            case 512:      W_well_emb = p; break;
            case 4800:     mlp_W2 = p; break;
            case 75:       mlp_b2 = p; break;
            case 12288:    if (n12288 < 2) a12288[n12288++] = p; break;
            case 4096:     if (n4096 < 3)  a4096[n4096++]   = p; break;
            case 192:      if (n192 < 4)   a192[n192++]     = p; break;
            case 64:       if (n64 < 8)    a64[n64++]       = p; break;
            default: break;
        }
        if (nf < 40) fsz[nf++] = sz;
    }

    int ord = 0;
    if (nf > 0 && fsz[0] == 768) ord = 1;
    else if (nf > 3 && fsz[0] == 64 && fsz[3] == 1600000) ord = 2;

    const float* conv_lin      = a12288[0];
    const float* conv_lin_edge = a12288[1];

    const float *conv_att_src, *conv_att_dst, *conv_att_edge, *conv_bias;
    if (ord == 0) { conv_att_src = a192[0]; conv_att_dst = a192[1];
                    conv_att_edge = a192[2]; conv_bias = a192[3]; }
    else          { conv_att_dst = a192[0]; conv_att_edge = a192[1];
                    conv_att_src = a192[2]; conv_bias = a192[3]; }

    const float *well_x, *wc_lin, *mlp_W1;
    if (ord == 0) { well_x = a4096[0]; wc_lin = a4096[1]; mlp_W1 = a4096[2]; }
    else          { mlp_W1 = a4096[0]; wc_lin = a4096[1]; well_x = a4096[2]; }

    const float *b_cell_emb, *b_well_emb, *W_edge_emb, *b_edge_emb,
                *wc_att_src, *wc_att_dst, *wc_bias, *mlp_b1;
    if (ord == 0) {
        b_cell_emb = a64[0]; b_well_emb = a64[1]; W_edge_emb = a64[2];
        b_edge_emb = a64[3]; wc_att_src = a64[4]; wc_att_dst = a64[5];
        wc_bias = a64[6]; mlp_b1 = a64[7];
    } else if (ord == 1) {
        W_edge_emb = a64[0]; b_cell_emb = a64[1]; b_edge_emb = a64[2];
        b_well_emb = a64[3]; mlp_b1 = a64[4]; wc_att_dst = a64[5];
        wc_att_src = a64[6]; wc_bias = a64[7];
    } else {
        b_cell_emb = a64[0]; b_edge_emb = a64[1]; b_well_emb = a64[2];
        mlp_b1 = a64[3]; W_edge_emb = a64[4]; wc_att_dst = a64[5];
        wc_att_src = a64[6]; wc_bias = a64[7];
    }

    const int NBLK_SCAN = (N_CELL + 1023) / 1024;    // 196
    const int NB_CELL = (N_CELL + 255) / 256;        // 782

    detect_idx64<<<1, 32>>>(cc_idx, cw_idx);
    compute_k<<<3, 64>>>(W_edge_emb, b_edge_emb, conv_lin_edge, conv_att_edge);
    prep_W0<<<4, 256>>>(W_cell_emb, b_cell_emb, conv_lin);

    // cell CSR
    zero_deg<<<NB_CELL, 256>>>();
    hist_cc<<<E_CC / 256, 256>>>(cc_idx);
    scan1<<<NBLK_SCAN, 1024>>>();
    scan2<<<1, 32>>>(NBLK_SCAN);
    scan3<<<NB_CELL, 256>>>();
    scatter_cc<<<E_CC / 256, 256>>>(cc_idx, attr);

    // well CSR
    wzero<<<2, 256>>>();
    whist<<<E_CW / 256, 256>>>(cw_idx);
    wscan<<<1, 512>>>();
    wscatter<<<E_CW / 256, 256>>>(cw_idx);

    // layer 0 (embedding folded into W0)
    gemm12<<<N_CELL / 64, 256>>>(cell_x, conv_att_src, conv_att_dst);
    pass_a_csr<<<NB_CELL, 256>>>(0);
    pass_b_csr<<<N_CELL / 8, 256>>>();

    // layers 1, 2
    for (int l = 1; l < 3; l++) {
        gemm_fused<<<N_CELL / 64, 256>>>(conv_lin + l * H * H,
                                         conv_att_src + l * H,
                                         conv_att_dst + l * H,
                                         conv_bias + (l - 1) * H);
        pass_a_csr<<<NB_CELL, 256>>>(l);
        pass_b_csr<<<N_CELL / 8, 256>>>();
    }

    // well GAT (finalize of layer 2 fused into this gemm's load)
    gemm_fused<<<N_CELL / 64, 256>>>(wc_lin, wc_att_src, wc_att_dst,
                                     conv_bias + 2 * H);
    well_prep<<<N_WELL, 64>>>(well_x, W_well_emb, b_well_emb, wc_lin, wc_att_dst);
    well_pass_a_csr<<<2, 256>>>();
    well_pass_b_csr<<<N_WELL / 8, 256>>>();
    well_finalize<<<N_WELL, 64>>>(wc_bias, mlp_W1, mlp_b1, mlp_W2, mlp_b2,
                                  (float*)d_out);
}

// round 11
// speedup vs baseline: 3.0918x; 1.0762x over previous
#include <cuda_runtime.h>

#define N_CELL 200000
#define N_WELL 512
#define E_CC   1600000
#define E_CW   65536
#define H      64
#define NEG_SLOPE 0.2f

// ---------------- scratch ----------------
__device__ float g_hs[N_CELL * H];
__device__ float g_num[N_CELL * H];
__device__ float g_as[N_CELL];
__device__ float g_ad[N_CELL];
__device__ float g_adw[N_WELL];
__device__ float g_numw[N_WELL * H];
__device__ float g_k1[3], g_k0[3];
__device__ float g_W0[12 * H];
__device__ float g_b0[H];
__device__ int g_cc64, g_cw64;

// CSR scratch
__device__ int g_off[N_CELL + 1];
__device__ int g_cur[N_CELL];
__device__ int g_srcp[E_CC];
__device__ float g_attrp[E_CC];
__device__ int g_bsum[256];
__device__ int g_woff[N_WELL + 1];
__device__ int g_wcur[N_WELL];
__device__ int g_wsrcp[E_CW];

// ---------------- f32x2 helpers ----------------
__device__ __forceinline__ unsigned long long pack2(float a) {
    unsigned long long r;
    asm("mov.b64 %0, {%1, %1};" : "=l"(r) : "f"(a));
    return r;
}
__device__ __forceinline__ void ffma2(unsigned long long& d,
                                      unsigned long long a,
                                      unsigned long long b) {
    asm("fma.rn.f32x2 %0, %1, %2, %0;" : "+l"(d) : "l"(a), "l"(b));
}
__device__ __forceinline__ float2 unpack2(unsigned long long v) {
    float2 f;
    asm("mov.b64 {%0, %1}, %2;" : "=f"(f.x), "=f"(f.y) : "l"(v));
    return f;
}

// ---------------- helpers ----------------
__global__ void detect_idx64(const void* cc, const void* cw) {
    if (threadIdx.x == 0) {
        const long long* q = (const long long*)cc;
        int ok = 1;
        for (int i = 0; i < 64; i++) {
            long long v = q[(long long)i * 25000];
            if (v < 0 || v >= N_CELL) { ok = 0; break; }
        }
        g_cc64 = ok;
        const long long* r = (const long long*)cw;
        ok = 1;
        for (int i = 0; i < 64; i++) {
            long long v = r[(long long)i * 1000];
            if (v < 0 || v >= N_CELL) { ok = 0; break; }
        }
        g_cw64 = ok;
    }
}

__device__ __forceinline__ int ld_idx(const void* p, long long i, int is64) {
    return is64 ? (int)((const long long*)p)[i] : ((const int*)p)[i];
}

// ---------------- k1/k0 + layer-0 weight fold ----------------
__global__ void compute_k(const float* __restrict__ W_edge,
                          const float* __restrict__ b_edge,
                          const float* __restrict__ lin_edge,
                          const float* __restrict__ att_e) {
    int l = blockIdx.x;
    int i = threadIdx.x;
    const float* L = lin_edge + l * H * H;
    const float* A = att_e + l * H;
    float r = 0.f;
    for (int j = 0; j < H; j++) r += L[i * H + j] * A[j];
    __shared__ float s1[H], s0[H];
    s1[i] = W_edge[i] * r;
    s0[i] = b_edge[i] * r;
    __syncthreads();
    if (i == 0) {
        float k1 = 0.f, k0 = 0.f;
        for (int j = 0; j < H; j++) { k1 += s1[j]; k0 += s0[j]; }
        g_k1[l] = k1; g_k0[l] = k0;
    }
}

__global__ void prep_W0(const float* __restrict__ Wemb,
                        const float* __restrict__ bemb,
                        const float* __restrict__ lin0) {
    int idx = blockIdx.x * blockDim.x + threadIdx.x;
    if (idx >= 13 * 64) return;
    int i = idx >> 6, c = idx & 63;
    float s = 0.f;
    if (i < 12) {
        for (int k = 0; k < H; k++) s += Wemb[i * H + k] * lin0[k * H + c];
        g_W0[i * H + c] = s;
    } else {
        for (int k = 0; k < H; k++) s += bemb[k] * lin0[k * H + c];
        g_b0[c] = s;
    }
}

// ---------------- CSR build (cells) ----------------
__global__ void zero_deg() {
    int i = blockIdx.x * blockDim.x + threadIdx.x;
    if (i < N_CELL) g_cur[i] = 0;
}
__global__ void hist_cc(const void* __restrict__ ei) {
    int e = blockIdx.x * blockDim.x + threadIdx.x;
    if (e >= E_CC) return;
    int d = ld_idx(ei, (long long)E_CC + e, g_cc64);
    atomicAdd(&g_cur[d], 1);
}
__global__ void scan1() {
    __shared__ int sh[1024];
    int tid = threadIdx.x;
    int gid = blockIdx.x * 1024 + tid;
    int v = (gid < N_CELL) ? g_cur[gid] : 0;
    sh[tid] = v;
    __syncthreads();
    for (int off = 1; off < 1024; off <<= 1) {
        int t = (tid >= off) ? sh[tid - off] : 0;
        __syncthreads();
        sh[tid] += t;
        __syncthreads();
    }
    if (gid < N_CELL) g_off[gid] = sh[tid] - v;
    if (tid == 1023) g_bsum[blockIdx.x] = sh[1023];
}
__global__ void scan2(int nblk) {
    if (threadIdx.x == 0) {
        int acc = 0;
        for (int b = 0; b < nblk; b++) { int t = g_bsum[b]; g_bsum[b] = acc; acc += t; }
        g_off[N_CELL] = E_CC;
    }
}
__global__ void scan3() {
    int gid = blockIdx.x * blockDim.x + threadIdx.x;
    if (gid >= N_CELL) return;
    int o = g_off[gid] + g_bsum[gid >> 10];
    g_off[gid] = o;
    g_cur[gid] = o;
}
__global__ void scatter_cc(const void* __restrict__ ei,
                           const float* __restrict__ attr) {
    int e = blockIdx.x * blockDim.x + threadIdx.x;
    if (e >= E_CC) return;
    int is64 = g_cc64;
    int s = ld_idx(ei, e, is64);
    int d = ld_idx(ei, (long long)E_CC + e, is64);
    int p = atomicAdd(&g_cur[d], 1);
    g_srcp[p] = s;
    g_attrp[p] = attr[e];
}

// ---------------- CSR build (wells) ----------------
__global__ void wzero() {
    int i = blockIdx.x * blockDim.x + threadIdx.x;
    if (i < N_WELL) g_wcur[i] = 0;
}
__global__ void whist(const void* __restrict__ ei) {
    int e = blockIdx.x * blockDim.x + threadIdx.x;
    if (e >= E_CW) return;
    int d = ld_idx(ei, (long long)E_CW + e, g_cw64);
    atomicAdd(&g_wcur[d], 1);
}
__global__ void wscan() {
    __shared__ int sh[512];
    int tid = threadIdx.x;
    int v = g_wcur[tid];
    sh[tid] = v;
    __syncthreads();
    for (int off = 1; off < 512; off <<= 1) {
        int t = (tid >= off) ? sh[tid - off] : 0;
        __syncthreads();
        sh[tid] += t;
        __syncthreads();
    }
    g_woff[tid] = sh[tid] - v;
    g_wcur[tid] = sh[tid] - v;
    if (tid == 0) g_woff[N_WELL] = E_CW;
}
__global__ void wscatter(const void* __restrict__ ei) {
    int e = blockIdx.x * blockDim.x + threadIdx.x;
    if (e >= E_CW) return;
    int is64 = g_cw64;
    int s = ld_idx(ei, e, is64);
    int d = ld_idx(ei, (long long)E_CW + e, is64);
    int p = atomicAdd(&g_wcur[d], 1);
    g_wsrcp[p] = s;
}

// ---------------- GEMM layer 0: hs = cell_x @ W0 + b0, fused att dots ----------------
__global__ __launch_bounds__(256) void gemm12(
    const float* __restrict__ x,
    const float* __restrict__ atts,
    const float* __restrict__ attd)
{
    __shared__ float shX[64][13];
    __shared__ float shW[12][64];
    __shared__ float shB[64];
    int tid = threadIdx.x;
    int r0 = blockIdx.x * 64;

    if (tid < 64) shB[tid] = g_b0[tid];
    for (int i = tid; i < 12 * 64; i += 256) shW[i >> 6][i & 63] = g_W0[i];
    for (int i = tid; i < 64 * 12; i += 256) shX[i / 12][i % 12] = x[(size_t)r0 * 12 + i];
    __syncthreads();

    int rg = tid >> 4, cg = tid & 15;
    int row0 = rg << 2, col0 = cg << 2;
    float acc[4][4];
    #pragma unroll
    for (int xx = 0; xx < 4; xx++)
        #pragma unroll
        for (int j = 0; j < 4; j++) acc[xx][j] = shB[col0 + j];

    #pragma unroll
    for (int k = 0; k < 12; k++) {
        float4 wv = *(const float4*)&shW[k][col0];
        float a0 = shX[row0][k], a1 = shX[row0 + 1][k];
        float a2 = shX[row0 + 2][k], a3 = shX[row0 + 3][k];
        acc[0][0] += a0 * wv.x; acc[0][1] += a0 * wv.y; acc[0][2] += a0 * wv.z; acc[0][3] += a0 * wv.w;
        acc[1][0] += a1 * wv.x; acc[1][1] += a1 * wv.y; acc[1][2] += a1 * wv.z; acc[1][3] += a1 * wv.w;
        acc[2][0] += a2 * wv.x; acc[2][1] += a2 * wv.y; acc[2][2] += a2 * wv.z; acc[2][3] += a2 * wv.w;
        acc[3][0] += a3 * wv.x; acc[3][1] += a3 * wv.y; acc[3][2] += a3 * wv.z; acc[3][3] += a3 * wv.w;
    }

    #pragma unroll
    for (int xx = 0; xx < 4; xx++) {
        float ps = acc[xx][0] * atts[col0] + acc[xx][1] * atts[col0 + 1]
                 + acc[xx][2] * atts[col0 + 2] + acc[xx][3] * atts[col0 + 3];
        float pd = acc[xx][0] * attd[col0] + acc[xx][1] * attd[col0 + 1]
                 + acc[xx][2] * attd[col0 + 2] + acc[xx][3] * attd[col0 + 3];
        #pragma unroll
        for (int off = 8; off; off >>= 1) {
            ps += __shfl_xor_sync(0xffffffffu, ps, off);
            pd += __shfl_xor_sync(0xffffffffu, pd, off);
        }
        if ((tid & 15) == 0) {
            g_as[r0 + row0 + xx] = ps;
            g_ad[r0 + row0 + xx] = pd;
        }
        *(float4*)&g_hs[(size_t)(r0 + row0 + xx) * H + col0] =
            make_float4(acc[xx][0], acc[xx][1], acc[xx][2], acc[xx][3]);
    }
}

// ---------------- GEMM layers 1+: hs = relu(g_num + bias) @ W  (f32x2) ----------------
__global__ __launch_bounds__(256) void gemm_fused(
    const float* __restrict__ W,
    const float* __restrict__ atts,
    const float* __restrict__ attd,
    const float* __restrict__ bias)
{
    __shared__ float shHT[64][68];   // TRANSPOSED input: shHT[k][row]
    __shared__ float shW[64][64];
    __shared__ float shB[64];
    int tid = threadIdx.x;
    int r0 = blockIdx.x * 64;

    if (tid < 64) shB[tid] = bias[tid];
    __syncthreads();

    const float4* W4 = (const float4*)W;
    for (int i = tid; i < 1024; i += 256) {
        int k = i >> 4, c = (i & 15) << 2;
        *(float4*)&shW[k][c] = W4[i];
    }
    const float4* src4 = (const float4*)g_num;
    for (int i = tid; i < 1024; i += 256) {
        float4 v = src4[(size_t)r0 * 16 + i];
        int rr = i >> 4, c = (i & 15) << 2;
        shHT[c][rr]     = fmaxf(v.x + shB[c], 0.f);
        shHT[c + 1][rr] = fmaxf(v.y + shB[c + 1], 0.f);
        shHT[c + 2][rr] = fmaxf(v.z + shB[c + 2], 0.f);
        shHT[c + 3][rr] = fmaxf(v.w + shB[c + 3], 0.f);
    }
    __syncthreads();

    int rg = tid >> 4, cg = tid & 15;
    int row0 = rg << 2, col0 = cg << 2;
    unsigned long long acc2[4][2] = {};

    #pragma unroll 8
    for (int k = 0; k < H; k++) {
        float4 av = *(const float4*)&shHT[k][row0];
        ulonglong2 wv = *(const ulonglong2*)&shW[k][col0];
        unsigned long long a0 = pack2(av.x), a1 = pack2(av.y);
        unsigned long long a2 = pack2(av.z), a3 = pack2(av.w);
        ffma2(acc2[0][0], a0, wv.x); ffma2(acc2[0][1], a0, wv.y);
        ffma2(acc2[1][0], a1, wv.x); ffma2(acc2[1][1], a1, wv.y);
        ffma2(acc2[2][0], a2, wv.x); ffma2(acc2[2][1], a2, wv.y);
        ffma2(acc2[3][0], a3, wv.x); ffma2(acc2[3][1], a3, wv.y);
    }

    #pragma unroll
    for (int xx = 0; xx < 4; xx++) {
        float2 p0 = unpack2(acc2[xx][0]);
        float2 p1 = unpack2(acc2[xx][1]);
        float ps = p0.x * atts[col0] + p0.y * atts[col0 + 1]
                 + p1.x * atts[col0 + 2] + p1.y * atts[col0 + 3];
        float pd = p0.x * attd[col0] + p0.y * attd[col0 + 1]
                 + p1.x * attd[col0 + 2] + p1.y * attd[col0 + 3];
        #pragma unroll
        for (int off = 8; off; off >>= 1) {
            ps += __shfl_xor_sync(0xffffffffu, ps, off);
            pd += __shfl_xor_sync(0xffffffffu, pd, off);
        }
        if ((tid & 15) == 0) {
            g_as[r0 + row0 + xx] = ps;
            g_ad[r0 + row0 + xx] = pd;
        }
        *(float4*)&g_hs[(size_t)(r0 + row0 + xx) * H + col0] =
            make_float4(p0.x, p0.y, p1.x, p1.y);
    }
}

// ---------------- fused edge pass (warp per dst): softmax + aggregate ----------------
// NOTE: the aggregate loop runs a UNIFORM iteration count across the warp so
// the __shfl_sync broadcasts are convergent (R10 crash: divergent shfl).
__global__ __launch_bounds__(256) void edge_fused(int l) {
    int w = (blockIdx.x * blockDim.x + threadIdx.x) >> 5;
    if (w >= N_CELL) return;
    int lane = threadIdx.x & 31;
    int half = lane >> 4, li = lane & 15;
    int beg = g_off[w], end = g_off[w + 1];
    int deg = end - beg;
    float adv = g_ad[w], k1 = g_k1[l], k0 = g_k0[l];

    float ssum = 0.f;
    float4 acc = make_float4(0.f, 0.f, 0.f, 0.f);

    for (int base = 0; base < deg; base += 32) {
        int n = min(32, deg - base);
        float ex = 0.f;
        int src = 0;
        if (lane < n) {
            src = g_srcp[beg + base + lane];
            float al = g_as[src] + adv + k1 * g_attrp[beg + base + lane] + k0;
            al = al > 0.f ? al : NEG_SLOPE * al;
            ex = __expf(al);
        }
        float cs = ex;
        #pragma unroll
        for (int off = 16; off; off >>= 1) cs += __shfl_xor_sync(0xffffffffu, cs, off);
        ssum += cs;
        // half-warps take alternate edges; uniform trip count, convergent shfl
        int iters = (n + 1) >> 1;
        for (int t = 0; t < iters; t++) {
            int j = 2 * t + half;
            int jj = j < n ? j : 0;
            float wt = __shfl_sync(0xffffffffu, ex, jj);
            int s2 = __shfl_sync(0xffffffffu, src, jj);
            if (j < n) {
                float4 v = *(const float4*)&g_hs[(size_t)s2 * H + li * 4];
                acc.x += v.x * wt; acc.y += v.y * wt; acc.z += v.z * wt; acc.w += v.w * wt;
            }
        }
    }
    acc.x += __shfl_down_sync(0xffffffffu, acc.x, 16);
    acc.y += __shfl_down_sync(0xffffffffu, acc.y, 16);
    acc.z += __shfl_down_sync(0xffffffffu, acc.z, 16);
    acc.w += __shfl_down_sync(0xffffffffu, acc.w, 16);
    if (lane < 16) {
        float sinv = deg > 0 ? 1.f / ssum : 0.f;
        *(float4*)&g_num[(size_t)w * H + li * 4] =
            make_float4(acc.x * sinv, acc.y * sinv, acc.z * sinv, acc.w * sinv);
    }
}

// ---------------- well path ----------------
__global__ void well_prep(const float* __restrict__ well_x,
                          const float* __restrict__ Ww,
                          const float* __restrict__ bw,
                          const float* __restrict__ wc_lin,
                          const float* __restrict__ attd) {
    int r = blockIdx.x;
    int c = threadIdx.x;
    __shared__ float hw[64];
    __shared__ float red[64];
    float acc = bw[c];
    for (int i = 0; i < 8; i++) acc += well_x[r * 8 + i] * Ww[i * H + c];
    hw[c] = acc;
    __syncthreads();
    float hd = 0.f;
    for (int k = 0; k < H; k++) hd += hw[k] * wc_lin[k * H + c];
    red[c] = hd * attd[c];
    __syncthreads();
    for (int off = 32; off > 0; off >>= 1) {
        if (c < off) red[c] += red[c + off];
        __syncthreads();
    }
    if (c == 0) g_adw[r] = red[0];
}

__global__ __launch_bounds__(256) void well_edge_fused() {
    int w = (blockIdx.x * blockDim.x + threadIdx.x) >> 5;
    if (w >= N_WELL) return;
    int lane = threadIdx.x & 31;
    int half = lane >> 4, li = lane & 15;
    int beg = g_woff[w], end = g_woff[w + 1];
    int deg = end - beg;
    float adv = g_adw[w];

    float ssum = 0.f;
    float4 acc = make_float4(0.f, 0.f, 0.f, 0.f);

    for (int base = 0; base < deg; base += 32) {
        int n = min(32, deg - base);
        float ex = 0.f;
        int src = 0;
        if (lane < n) {
            src = g_wsrcp[beg + base + lane];
            float al = g_as[src] + adv;
            al = al > 0.f ? al : NEG_SLOPE * al;
            ex = __expf(al);
        }
        float cs = ex;
        #pragma unroll
        for (int off = 16; off; off >>= 1) cs += __shfl_xor_sync(0xffffffffu, cs, off);
        ssum += cs;
        int iters = (n + 1) >> 1;
        for (int t = 0; t < iters; t++) {
            int j = 2 * t + half;
            int jj = j < n ? j : 0;
            float wt = __shfl_sync(0xffffffffu, ex, jj);
            int s2 = __shfl_sync(0xffffffffu, src, jj);
            if (j < n) {
                float4 v = *(const float4*)&g_hs[(size_t)s2 * H + li * 4];
                acc.x += v.x * wt; acc.y += v.y * wt; acc.z += v.z * wt; acc.w += v.w * wt;
            }
        }
    }
    acc.x += __shfl_down_sync(0xffffffffu, acc.x, 16);
    acc.y += __shfl_down_sync(0xffffffffu, acc.y, 16);
    acc.z += __shfl_down_sync(0xffffffffu, acc.z, 16);
    acc.w += __shfl_down_sync(0xffffffffu, acc.w, 16);
    if (lane < 16) {
        float sinv = deg > 0 ? 1.f / ssum : 0.f;
        *(float4*)&g_numw[(size_t)w * H + li * 4] =
            make_float4(acc.x * sinv, acc.y * sinv, acc.z * sinv, acc.w * sinv);
    }
}

__global__ void well_finalize(const float* __restrict__ wc_bias,
                              const float* __restrict__ W1,
                              const float* __restrict__ b1,
                              const float* __restrict__ W2,
                              const float* __restrict__ b2,
                              float* __restrict__ out) {
    int r = blockIdx.x;
    int c = threadIdx.x;
    __shared__ float hwell[64];
    __shared__ float t1[64];
    hwell[c] = g_numw[r * H + c] + wc_bias[c];
    __syncthreads();
    float a = b1[c];
    for (int k = 0; k < H; k++) a += hwell[k] * W1[k * H + c];
    t1[c] = fmaxf(a, 0.f);
    __syncthreads();
    for (int o = c; o < 75; o += 64) {
        float acc = b2[o];
        for (int k = 0; k < H; k++) acc += t1[k] * W2[k * 75 + o];
        out[r * 75 + o] = acc;
    }
}

// ---------------- launcher ----------------
extern "C" void kernel_launch(void* const* d_in, const int* in_sizes, int n_in,
                              void* d_out, int out_size) {
    const void* cc_idx = nullptr;
    const void* cw_idx = nullptr;
    const float *cell_x = nullptr, *attr = nullptr, *W_cell_emb = nullptr,
                *W_well_emb = nullptr, *mlp_W2 = nullptr, *mlp_b2 = nullptr;
    const float* a12288[2] = {nullptr, nullptr};
    const float* a4096[3]  = {nullptr, nullptr, nullptr};
    const float* a192[4]   = {nullptr, nullptr, nullptr, nullptr};
    const float* a64[8]    = {nullptr, nullptr, nullptr, nullptr,
                              nullptr, nullptr, nullptr, nullptr};
    int n12288 = 0, n4096 = 0, n192 = 0, n64 = 0;
    int fsz[40]; int nf = 0;

    for (int i = 0; i < n_in; i++) {
        int sz = in_sizes[i];
        const float* p = (const float*)d_in[i];
        switch (sz) {
            case 2 * E_CC: cc_idx = d_in[i]; continue;
            case 2 * E_CW: cw_idx = d_in[i]; continue;
            case 2400000:  cell_x = p; break;
            case 1600000:  attr = p; break;
            case 768:      W_cell_emb = p; break;
            case 512:      W_well_emb = p; break;
            case 4800:     mlp_W2 = p; break;
            case 75:       mlp_b2 = p; break;
            case 12288:    if (n12288 < 2) a12288[n12288++] = p; break;
            case 4096:     if (n4096 < 3)  a4096[n4096++]   = p; break;
            case 192:      if (n192 < 4)   a192[n192++]     = p; break;
            case 64:       if (n64 < 8)    a64[n64++]       = p; break;
            default: break;
        }
        if (nf < 40) fsz[nf++] = sz;
    }

    int ord = 0;
    if (nf > 0 && fsz[0] == 768) ord = 1;
    else if (nf > 3 && fsz[0] == 64 && fsz[3] == 1600000) ord = 2;

    const float* conv_lin      = a12288[0];
    const float* conv_lin_edge = a12288[1];

    const float *conv_att_src, *conv_att_dst, *conv_att_edge, *conv_bias;
    if (ord == 0) { conv_att_src = a192[0]; conv_att_dst = a192[1];
                    conv_att_edge = a192[2]; conv_bias = a192[3]; }
    else          { conv_att_dst = a192[0]; conv_att_edge = a192[1];
                    conv_att_src = a192[2]; conv_bias = a192[3]; }

    const float *well_x, *wc_lin, *mlp_W1;
    if (ord == 0) { well_x = a4096[0]; wc_lin = a4096[1]; mlp_W1 = a4096[2]; }
    else          { mlp_W1 = a4096[0]; wc_lin = a4096[1]; well_x = a4096[2]; }

    const float *b_cell_emb, *b_well_emb, *W_edge_emb, *b_edge_emb,
                *wc_att_src, *wc_att_dst, *wc_bias, *mlp_b1;
    if (ord == 0) {
        b_cell_emb = a64[0]; b_well_emb = a64[1]; W_edge_emb = a64[2];
        b_edge_emb = a64[3]; wc_att_src = a64[4]; wc_att_dst = a64[5];
        wc_bias = a64[6]; mlp_b1 = a64[7];
    } else if (ord == 1) {
        W_edge_emb = a64[0]; b_cell_emb = a64[1]; b_edge_emb = a64[2];
        b_well_emb = a64[3]; mlp_b1 = a64[4]; wc_att_dst = a64[5];
        wc_att_src = a64[6]; wc_bias = a64[7];
    } else {
        b_cell_emb = a64[0]; b_edge_emb = a64[1]; b_well_emb = a64[2];
        mlp_b1 = a64[3]; W_edge_emb = a64[4]; wc_att_dst = a64[5];
        wc_att_src = a64[6]; wc_bias = a64[7];
    }

    const int NBLK_SCAN = (N_CELL + 1023) / 1024;
    const int NB_CELL = (N_CELL + 255) / 256;

    detect_idx64<<<1, 32>>>(cc_idx, cw_idx);
    compute_k<<<3, 64>>>(W_edge_emb, b_edge_emb, conv_lin_edge, conv_att_edge);
    prep_W0<<<4, 256>>>(W_cell_emb, b_cell_emb, conv_lin);

    // cell CSR
    zero_deg<<<NB_CELL, 256>>>();
    hist_cc<<<E_CC / 256, 256>>>(cc_idx);
    scan1<<<NBLK_SCAN, 1024>>>();
    scan2<<<1, 32>>>(NBLK_SCAN);
    scan3<<<NB_CELL, 256>>>();
    scatter_cc<<<E_CC / 256, 256>>>(cc_idx, attr);

    // well CSR
    wzero<<<2, 256>>>();
    whist<<<E_CW / 256, 256>>>(cw_idx);
    wscan<<<1, 512>>>();
    wscatter<<<E_CW / 256, 256>>>(cw_idx);

    // layer 0 (embedding folded into W0)
    gemm12<<<N_CELL / 64, 256>>>(cell_x, conv_att_src, conv_att_dst);
    edge_fused<<<N_CELL / 8, 256>>>(0);

    // layers 1, 2
    for (int l = 1; l < 3; l++) {
        gemm_fused<<<N_CELL / 64, 256>>>(conv_lin + l * H * H,
                                         conv_att_src + l * H,
                                         conv_att_dst + l * H,
                                         conv_bias + (l - 1) * H);
        edge_fused<<<N_CELL / 8, 256>>>(l);
    }

    // well GAT
    gemm_fused<<<N_CELL / 64, 256>>>(wc_lin, wc_att_src, wc_att_dst,
                                     conv_bias + 2 * H);
    well_prep<<<N_WELL, 64>>>(well_x, W_well_emb, b_well_emb, wc_lin, wc_att_dst);
    well_edge_fused<<<N_WELL / 8, 256>>>();
    well_finalize<<<N_WELL, 64>>>(wc_bias, mlp_W1, mlp_b1, mlp_W2, mlp_b2,
                                  (float*)d_out);
}

// round 12
// speedup vs baseline: 3.2173x; 1.0406x over previous
#include <cuda_runtime.h>

#define N_CELL 200000
#define N_WELL 512
#define E_CC   1600000
#define E_CW   65536
#define H      64
#define NEG_SLOPE 0.2f

// ---------------- scratch ----------------
__device__ float g_hs[N_CELL * H];
__device__ float g_num[N_CELL * H];
__device__ float g_as[N_CELL];
__device__ float g_ad[N_CELL];
__device__ float g_adw[N_WELL];
__device__ float g_numw[N_WELL * H];
__device__ float g_k1[3], g_k0[3];
__device__ float g_W0[12 * H];
__device__ float g_b0[H];
__device__ int g_cc64, g_cw64;

// CSR scratch
__device__ int g_off[N_CELL + 1];
__device__ int g_cur[N_CELL];
__device__ int g_srcp[E_CC];
__device__ float g_attrp[E_CC];
__device__ int g_bsum[256];
__device__ int g_woff[N_WELL + 1];
__device__ int g_wcur[N_WELL];
__device__ int g_wsrcp[E_CW];

// ---------------- f32x2 helpers ----------------
__device__ __forceinline__ unsigned long long pack2(float a) {
    unsigned long long r;
    asm("mov.b64 %0, {%1, %1};" : "=l"(r) : "f"(a));
    return r;
}
__device__ __forceinline__ void ffma2(unsigned long long& d,
                                      unsigned long long a,
                                      unsigned long long b) {
    asm("fma.rn.f32x2 %0, %1, %2, %0;" : "+l"(d) : "l"(a), "l"(b));
}
__device__ __forceinline__ float2 unpack2(unsigned long long v) {
    float2 f;
    asm("mov.b64 {%0, %1}, %2;" : "=f"(f.x), "=f"(f.y) : "l"(v));
    return f;
}

__device__ __forceinline__ int ld_idx(const void* p, long long i, int is64) {
    return is64 ? (int)((const long long*)p)[i] : ((const int*)p)[i];
}

// ---------------- setup: detect idx width + compute_k + prep_W0 (merged) ----------------
__global__ void setup(const float* __restrict__ W_edge,
                      const float* __restrict__ b_edge,
                      const float* __restrict__ lin_edge,
                      const float* __restrict__ att_e,
                      const float* __restrict__ Wemb,
                      const float* __restrict__ bemb,
                      const float* __restrict__ lin0,
                      const void* cc, const void* cw) {
    int b = blockIdx.x;
    int tid = threadIdx.x;
    if (b == 0) {
        if (tid == 0) {
            const long long* q = (const long long*)cc;
            int ok = 1;
            for (int i = 0; i < 64; i++) {
                long long v = q[(long long)i * 25000];
                if (v < 0 || v >= N_CELL) { ok = 0; break; }
            }
            g_cc64 = ok;
            const long long* r = (const long long*)cw;
            ok = 1;
            for (int i = 0; i < 64; i++) {
                long long v = r[(long long)i * 1000];
                if (v < 0 || v >= N_CELL) { ok = 0; break; }
            }
            g_cw64 = ok;
        }
    } else if (b <= 3) {
        // compute_k for layer l = b-1
        int l = b - 1;
        __shared__ float s1[H], s0[H];
        if (tid < H) {
            const float* L = lin_edge + l * H * H;
            const float* A = att_e + l * H;
            float r = 0.f;
            for (int j = 0; j < H; j++) r += L[tid * H + j] * A[j];
            s1[tid] = W_edge[tid] * r;
            s0[tid] = b_edge[tid] * r;
        }
        __syncthreads();
        if (tid == 0) {
            float k1 = 0.f, k0 = 0.f;
            for (int j = 0; j < H; j++) { k1 += s1[j]; k0 += s0[j]; }
            g_k1[l] = k1; g_k0[l] = k0;
        }
    } else {
        // prep_W0: idx over 13*64 = 832 entries, blocks 4..7
        int idx = (b - 4) * 256 + tid;
        if (idx < 13 * 64) {
            int i = idx >> 6, c = idx & 63;
            float s = 0.f;
            if (i < 12) {
                for (int k = 0; k < H; k++) s += Wemb[i * H + k] * lin0[k * H + c];
                g_W0[i * H + c] = s;
            } else {
                for (int k = 0; k < H; k++) s += bemb[k] * lin0[k * H + c];
                g_b0[c] = s;
            }
        }
    }
}

// ---------------- CSR build (cells + wells merged where possible) ----------------
__global__ void zero_all() {
    int i = blockIdx.x * blockDim.x + threadIdx.x;
    if (i < N_CELL) g_cur[i] = 0;
    if (i < N_WELL) g_wcur[i] = 0;
}
__global__ void hist_all(const void* __restrict__ cc, const void* __restrict__ cw) {
    int e = blockIdx.x * blockDim.x + threadIdx.x;
    if (e < E_CC) {
        int d = ld_idx(cc, (long long)E_CC + e, g_cc64);
        atomicAdd(&g_cur[d], 1);
    } else if (e < E_CC + E_CW) {
        int e2 = e - E_CC;
        int d = ld_idx(cw, (long long)E_CW + e2, g_cw64);
        atomicAdd(&g_wcur[d], 1);
    }
}
__global__ void scan1() {
    __shared__ int sh[1024];
    int tid = threadIdx.x;
    int gid = blockIdx.x * 1024 + tid;
    int v = (gid < N_CELL) ? g_cur[gid] : 0;
    sh[tid] = v;
    __syncthreads();
    for (int off = 1; off < 1024; off <<= 1) {
        int t = (tid >= off) ? sh[tid - off] : 0;
        __syncthreads();
        sh[tid] += t;
        __syncthreads();
    }
    if (gid < N_CELL) g_off[gid] = sh[tid] - v;
    if (tid == 1023) g_bsum[blockIdx.x] = sh[1023];
}
__global__ void scan2p(int nblk) {
    __shared__ int sh[256];
    int tid = threadIdx.x;
    int v = tid < nblk ? g_bsum[tid] : 0;
    sh[tid] = v;
    __syncthreads();
    for (int off = 1; off < 256; off <<= 1) {
        int t = (tid >= off) ? sh[tid - off] : 0;
        __syncthreads();
        sh[tid] += t;
        __syncthreads();
    }
    if (tid < nblk) g_bsum[tid] = sh[tid] - v;   // exclusive block offsets
    if (tid == 0) g_off[N_CELL] = E_CC;
}
__global__ void scan3() {
    int gid = blockIdx.x * blockDim.x + threadIdx.x;
    if (gid >= N_CELL) return;
    int o = g_off[gid] + g_bsum[gid >> 10];
    g_off[gid] = o;
    g_cur[gid] = o;
}
__global__ void wscan() {
    __shared__ int sh[512];
    int tid = threadIdx.x;
    int v = g_wcur[tid];
    sh[tid] = v;
    __syncthreads();
    for (int off = 1; off < 512; off <<= 1) {
        int t = (tid >= off) ? sh[tid - off] : 0;
        __syncthreads();
        sh[tid] += t;
        __syncthreads();
    }
    g_woff[tid] = sh[tid] - v;
    g_wcur[tid] = sh[tid] - v;
    if (tid == 0) g_woff[N_WELL] = E_CW;
}
__global__ void scatter_all(const void* __restrict__ cc,
                            const void* __restrict__ cw,
                            const float* __restrict__ attr) {
    int e = blockIdx.x * blockDim.x + threadIdx.x;
    if (e < E_CC) {
        int is64 = g_cc64;
        int s = ld_idx(cc, e, is64);
        int d = ld_idx(cc, (long long)E_CC + e, is64);
        int p = atomicAdd(&g_cur[d], 1);
        g_srcp[p] = s;
        g_attrp[p] = attr[e];
    } else if (e < E_CC + E_CW) {
        int e2 = e - E_CC;
        int is64 = g_cw64;
        int s = ld_idx(cw, e2, is64);
        int d = ld_idx(cw, (long long)E_CW + e2, is64);
        int p = atomicAdd(&g_wcur[d], 1);
        g_wsrcp[p] = s;
    }
}

// ---------------- GEMM layer 0: hs = cell_x @ W0 + b0, fused att dots ----------------
__global__ __launch_bounds__(256) void gemm12(
    const float* __restrict__ x,
    const float* __restrict__ atts,
    const float* __restrict__ attd)
{
    __shared__ float shX[64][13];
    __shared__ float shW[12][64];
    __shared__ float shB[64];
    int tid = threadIdx.x;
    int r0 = blockIdx.x * 64;

    if (tid < 64) shB[tid] = g_b0[tid];
    for (int i = tid; i < 12 * 64; i += 256) shW[i >> 6][i & 63] = g_W0[i];
    for (int i = tid; i < 64 * 12; i += 256) shX[i / 12][i % 12] = x[(size_t)r0 * 12 + i];
    __syncthreads();

    int rg = tid >> 4, cg = tid & 15;
    int row0 = rg << 2, col0 = cg << 2;
    float acc[4][4];
    #pragma unroll
    for (int xx = 0; xx < 4; xx++)
        #pragma unroll
        for (int j = 0; j < 4; j++) acc[xx][j] = shB[col0 + j];

    #pragma unroll
    for (int k = 0; k < 12; k++) {
        float4 wv = *(const float4*)&shW[k][col0];
        float a0 = shX[row0][k], a1 = shX[row0 + 1][k];
        float a2 = shX[row0 + 2][k], a3 = shX[row0 + 3][k];
        acc[0][0] += a0 * wv.x; acc[0][1] += a0 * wv.y; acc[0][2] += a0 * wv.z; acc[0][3] += a0 * wv.w;
        acc[1][0] += a1 * wv.x; acc[1][1] += a1 * wv.y; acc[1][2] += a1 * wv.z; acc[1][3] += a1 * wv.w;
        acc[2][0] += a2 * wv.x; acc[2][1] += a2 * wv.y; acc[2][2] += a2 * wv.z; acc[2][3] += a2 * wv.w;
        acc[3][0] += a3 * wv.x; acc[3][1] += a3 * wv.y; acc[3][2] += a3 * wv.z; acc[3][3] += a3 * wv.w;
    }

    #pragma unroll
    for (int xx = 0; xx < 4; xx++) {
        float ps = acc[xx][0] * atts[col0] + acc[xx][1] * atts[col0 + 1]
                 + acc[xx][2] * atts[col0 + 2] + acc[xx][3] * atts[col0 + 3];
        float pd = acc[xx][0] * attd[col0] + acc[xx][1] * attd[col0 + 1]
                 + acc[xx][2] * attd[col0 + 2] + acc[xx][3] * attd[col0 + 3];
        #pragma unroll
        for (int off = 8; off; off >>= 1) {
            ps += __shfl_xor_sync(0xffffffffu, ps, off);
            pd += __shfl_xor_sync(0xffffffffu, pd, off);
        }
        if ((tid & 15) == 0) {
            g_as[r0 + row0 + xx] = ps;
            g_ad[r0 + row0 + xx] = pd;
        }
        *(float4*)&g_hs[(size_t)(r0 + row0 + xx) * H + col0] =
            make_float4(acc[xx][0], acc[xx][1], acc[xx][2], acc[xx][3]);
    }
}

// ---------------- GEMM layers 1+: hs = relu(g_num + bias) @ W  (f32x2) ----------------
__global__ __launch_bounds__(256) void gemm_fused(
    const float* __restrict__ W,
    const float* __restrict__ atts,
    const float* __restrict__ attd,
    const float* __restrict__ bias)
{
    __shared__ float shHT[64][68];
    __shared__ float shW[64][64];
    __shared__ float shB[64];
    int tid = threadIdx.x;
    int r0 = blockIdx.x * 64;

    if (tid < 64) shB[tid] = bias[tid];
    __syncthreads();

    const float4* W4 = (const float4*)W;
    for (int i = tid; i < 1024; i += 256) {
        int k = i >> 4, c = (i & 15) << 2;
        *(float4*)&shW[k][c] = W4[i];
    }
    const float4* src4 = (const float4*)g_num;
    for (int i = tid; i < 1024; i += 256) {
        float4 v = src4[(size_t)r0 * 16 + i];
        int rr = i >> 4, c = (i & 15) << 2;
        shHT[c][rr]     = fmaxf(v.x + shB[c], 0.f);
        shHT[c + 1][rr] = fmaxf(v.y + shB[c + 1], 0.f);
        shHT[c + 2][rr] = fmaxf(v.z + shB[c + 2], 0.f);
        shHT[c + 3][rr] = fmaxf(v.w + shB[c + 3], 0.f);
    }
    __syncthreads();

    int rg = tid >> 4, cg = tid & 15;
    int row0 = rg << 2, col0 = cg << 2;
    unsigned long long acc2[4][2] = {};

    #pragma unroll 8
    for (int k = 0; k < H; k++) {
        float4 av = *(const float4*)&shHT[k][row0];
        ulonglong2 wv = *(const ulonglong2*)&shW[k][col0];
        unsigned long long a0 = pack2(av.x), a1 = pack2(av.y);
        unsigned long long a2 = pack2(av.z), a3 = pack2(av.w);
        ffma2(acc2[0][0], a0, wv.x); ffma2(acc2[0][1], a0, wv.y);
        ffma2(acc2[1][0], a1, wv.x); ffma2(acc2[1][1], a1, wv.y);
        ffma2(acc2[2][0], a2, wv.x); ffma2(acc2[2][1], a2, wv.y);
        ffma2(acc2[3][0], a3, wv.x); ffma2(acc2[3][1], a3, wv.y);
    }

    #pragma unroll
    for (int xx = 0; xx < 4; xx++) {
        float2 p0 = unpack2(acc2[xx][0]);
        float2 p1 = unpack2(acc2[xx][1]);
        float ps = p0.x * atts[col0] + p0.y * atts[col0 + 1]
                 + p1.x * atts[col0 + 2] + p1.y * atts[col0 + 3];
        float pd = p0.x * attd[col0] + p0.y * attd[col0 + 1]
                 + p1.x * attd[col0 + 2] + p1.y * attd[col0 + 3];
        #pragma unroll
        for (int off = 8; off; off >>= 1) {
            ps += __shfl_xor_sync(0xffffffffu, ps, off);
            pd += __shfl_xor_sync(0xffffffffu, pd, off);
        }
        if ((tid & 15) == 0) {
            g_as[r0 + row0 + xx] = ps;
            g_ad[r0 + row0 + xx] = pd;
        }
        *(float4*)&g_hs[(size_t)(r0 + row0 + xx) * H + col0] =
            make_float4(p0.x, p0.y, p1.x, p1.y);
    }
}

// ---------------- fused edge pass (warp per dst): softmax + aggregate ----------------
__global__ __launch_bounds__(256) void edge_fused(int l) {
    int w = (blockIdx.x * blockDim.x + threadIdx.x) >> 5;
    if (w >= N_CELL) return;
    int lane = threadIdx.x & 31;
    int half = lane >> 4, li = lane & 15;
    int beg = g_off[w], end = g_off[w + 1];
    int deg = end - beg;
    float adv = g_ad[w], k1 = g_k1[l], k0 = g_k0[l];

    float ssum = 0.f;
    float4 acc = make_float4(0.f, 0.f, 0.f, 0.f);

    for (int base = 0; base < deg; base += 32) {
        int n = min(32, deg - base);
        float ex = 0.f;
        int src = 0;
        if (lane < n) {
            src = g_srcp[beg + base + lane];
            float al = g_as[src] + adv + k1 * g_attrp[beg + base + lane] + k0;
            al = al > 0.f ? al : NEG_SLOPE * al;
            ex = __expf(al);
        }
        float cs = ex;
        #pragma unroll
        for (int off = 16; off; off >>= 1) cs += __shfl_xor_sync(0xffffffffu, cs, off);
        ssum += cs;
        int iters = (n + 1) >> 1;
        for (int t = 0; t < iters; t++) {
            int j = 2 * t + half;
            int jj = j < n ? j : 0;
            float wt = __shfl_sync(0xffffffffu, ex, jj);
            int s2 = __shfl_sync(0xffffffffu, src, jj);
            if (j < n) {
                float4 v = *(const float4*)&g_hs[(size_t)s2 * H + li * 4];
                acc.x += v.x * wt; acc.y += v.y * wt; acc.z += v.z * wt; acc.w += v.w * wt;
            }
        }
    }
    acc.x += __shfl_down_sync(0xffffffffu, acc.x, 16);
    acc.y += __shfl_down_sync(0xffffffffu, acc.y, 16);
    acc.z += __shfl_down_sync(0xffffffffu, acc.z, 16);
    acc.w += __shfl_down_sync(0xffffffffu, acc.w, 16);
    if (lane < 16) {
        float sinv = deg > 0 ? 1.f / ssum : 0.f;
        *(float4*)&g_num[(size_t)w * H + li * 4] =
            make_float4(acc.x * sinv, acc.y * sinv, acc.z * sinv, acc.w * sinv);
    }
}

// ---------------- well path ----------------
__global__ void well_prep(const float* __restrict__ well_x,
                          const float* __restrict__ Ww,
                          const float* __restrict__ bw,
                          const float* __restrict__ wc_lin,
                          const float* __restrict__ attd) {
    int r = blockIdx.x;
    int c = threadIdx.x;
    __shared__ float hw[64];
    __shared__ float red[64];
    float acc = bw[c];
    for (int i = 0; i < 8; i++) acc += well_x[r * 8 + i] * Ww[i * H + c];
    hw[c] = acc;
    __syncthreads();
    float hd = 0.f;
    for (int k = 0; k < H; k++) hd += hw[k] * wc_lin[k * H + c];
    red[c] = hd * attd[c];
    __syncthreads();
    for (int off = 32; off > 0; off >>= 1) {
        if (c < off) red[c] += red[c + off];
        __syncthreads();
    }
    if (c == 0) g_adw[r] = red[0];
}

__global__ __launch_bounds__(256) void well_edge_fused() {
    int w = (blockIdx.x * blockDim.x + threadIdx.x) >> 5;
    if (w >= N_WELL) return;
    int lane = threadIdx.x & 31;
    int half = lane >> 4, li = lane & 15;
    int beg = g_woff[w], end = g_woff[w + 1];
    int deg = end - beg;
    float adv = g_adw[w];

    float ssum = 0.f;
    float4 acc = make_float4(0.f, 0.f, 0.f, 0.f);

    for (int base = 0; base < deg; base += 32) {
        int n = min(32, deg - base);
        float ex = 0.f;
        int src = 0;
        if (lane < n) {
            src = g_wsrcp[beg + base + lane];
            float al = g_as[src] + adv;
            al = al > 0.f ? al : NEG_SLOPE * al;
            ex = __expf(al);
        }
        float cs = ex;
        #pragma unroll
        for (int off = 16; off; off >>= 1) cs += __shfl_xor_sync(0xffffffffu, cs, off);
        ssum += cs;
        int iters = (n + 1) >> 1;
        for (int t = 0; t < iters; t++) {
            int j = 2 * t + half;
            int jj = j < n ? j : 0;
            float wt = __shfl_sync(0xffffffffu, ex, jj);
            int s2 = __shfl_sync(0xffffffffu, src, jj);
            if (j < n) {
                float4 v = *(const float4*)&g_hs[(size_t)s2 * H + li * 4];
                acc.x += v.x * wt; acc.y += v.y * wt; acc.z += v.z * wt; acc.w += v.w * wt;
            }
        }
    }
    acc.x += __shfl_down_sync(0xffffffffu, acc.x, 16);
    acc.y += __shfl_down_sync(0xffffffffu, acc.y, 16);
    acc.z += __shfl_down_sync(0xffffffffu, acc.z, 16);
    acc.w += __shfl_down_sync(0xffffffffu, acc.w, 16);
    if (lane < 16) {
        float sinv = deg > 0 ? 1.f / ssum : 0.f;
        *(float4*)&g_numw[(size_t)w * H + li * 4] =
            make_float4(acc.x * sinv, acc.y * sinv, acc.z * sinv, acc.w * sinv);
    }
}

__global__ void well_finalize(const float* __restrict__ wc_bias,
                              const float* __restrict__ W1,
                              const float* __restrict__ b1,
                              const float* __restrict__ W2,
                              const float* __restrict__ b2,
                              float* __restrict__ out) {
    int r = blockIdx.x;
    int c = threadIdx.x;
    __shared__ float hwell[64];
    __shared__ float t1[64];
    hwell[c] = g_numw[r * H + c] + wc_bias[c];
    __syncthreads();
    float a = b1[c];
    for (int k = 0; k < H; k++) a += hwell[k] * W1[k * H + c];
    t1[c] = fmaxf(a, 0.f);
    __syncthreads();
    for (int o = c; o < 75; o += 64) {
        float acc = b2[o];
        for (int k = 0; k < H; k++) acc += t1[k] * W2[k * 75 + o];
        out[r * 75 + o] = acc;
    }
}

// ---------------- launcher ----------------
extern "C" void kernel_launch(void* const* d_in, const int* in_sizes, int n_in,
                              void* d_out, int out_size) {
    const void* cc_idx = nullptr;
    const void* cw_idx = nullptr;
    const float *cell_x = nullptr, *attr = nullptr, *W_cell_emb = nullptr,
                *W_well_emb = nullptr, *mlp_W2 = nullptr, *mlp_b2 = nullptr;
    const float* a12288[2] = {nullptr, nullptr};
    const float* a4096[3]  = {nullptr, nullptr, nullptr};
    const float* a192[4]   = {nullptr, nullptr, nullptr, nullptr};
    const float* a64[8]    = {nullptr, nullptr, nullptr, nullptr,
                              nullptr, nullptr, nullptr, nullptr};
    int n12288 = 0, n4096 = 0, n192 = 0, n64 = 0;
    int fsz[40]; int nf = 0;

    for (int i = 0; i < n_in; i++) {
        int sz = in_sizes[i];
        const float* p = (const float*)d_in[i];
        switch (sz) {
            case 2 * E_CC: cc_idx = d_in[i]; continue;
            case 2 * E_CW: cw_idx = d_in[i]; continue;
            case 2400000:  cell_x = p; break;
            case 1600000:  attr = p; break;
            case 768:      W_cell_emb = p; break;
            case 512:      W_well_emb = p; break;
            case 4800:     mlp_W2 = p; break;
            case 75:       mlp_b2 = p; break;
            case 12288:    if (n12288 < 2) a12288[n12288++] = p; break;
            case 4096:     if (n4096 < 3)  a4096[n4096++]   = p; break;
            case 192:      if (n192 < 4)   a192[n192++]     = p; break;
            case 64:       if (n64 < 8)    a64[n64++]       = p; break;
            default: break;
        }
        if (nf < 40) fsz[nf++] = sz;
    }

    int ord = 0;
    if (nf > 0 && fsz[0] == 768) ord = 1;
    else if (nf > 3 && fsz[0] == 64 && fsz[3] == 1600000) ord = 2;

    const float* conv_lin      = a12288[0];
    const float* conv_lin_edge = a12288[1];

    const float *conv_att_src, *conv_att_dst, *conv_att_edge, *conv_bias;
    if (ord == 0) { conv_att_src = a192[0]; conv_att_dst = a192[1];
                    conv_att_edge = a192[2]; conv_bias = a192[3]; }
    else          { conv_att_dst = a192[0]; conv_att_edge = a192[1];
                    conv_att_src = a192[2]; conv_bias = a192[3]; }

    const float *well_x, *wc_lin, *mlp_W1;
    if (ord == 0) { well_x = a4096[0]; wc_lin = a4096[1]; mlp_W1 = a4096[2]; }
    else          { mlp_W1 = a4096[0]; wc_lin = a4096[1]; well_x = a4096[2]; }

    const float *b_cell_emb, *b_well_emb, *W_edge_emb, *b_edge_emb,
                *wc_att_src, *wc_att_dst, *wc_bias, *mlp_b1;
    if (ord == 0) {
        b_cell_emb = a64[0]; b_well_emb = a64[1]; W_edge_emb = a64[2];
        b_edge_emb = a64[3]; wc_att_src = a64[4]; wc_att_dst = a64[5];
        wc_bias = a64[6]; mlp_b1 = a64[7];
    } else if (ord == 1) {
        W_edge_emb = a64[0]; b_cell_emb = a64[1]; b_edge_emb = a64[2];
        b_well_emb = a64[3]; mlp_b1 = a64[4]; wc_att_dst = a64[5];
        wc_att_src = a64[6]; wc_bias = a64[7];
    } else {
        b_cell_emb = a64[0]; b_edge_emb = a64[1]; b_well_emb = a64[2];
        mlp_b1 = a64[3]; W_edge_emb = a64[4]; wc_att_dst = a64[5];
        wc_att_src = a64[6]; wc_bias = a64[7];
    }

    // one-time host-side resources (no device memory involved)
    static cudaStream_t s_side = nullptr;
    static cudaEvent_t e_det = nullptr, e_csr = nullptr;
    if (!s_side) {
        cudaStreamCreateWithFlags(&s_side, cudaStreamNonBlocking);
        cudaEventCreateWithFlags(&e_det, cudaEventDisableTiming);
        cudaEventCreateWithFlags(&e_csr, cudaEventDisableTiming);
    }

    const int NBLK_SCAN = (N_CELL + 1023) / 1024;   // 196
    const int NB_CELL = (N_CELL + 255) / 256;       // 782
    const int NB_EALL = (E_CC + E_CW) / 256;        // 6506

    // main stream: setup (detect + k-fold + W0-fold)
    setup<<<8, 256>>>(W_edge_emb, b_edge_emb, conv_lin_edge, conv_att_edge,
                      W_cell_emb, b_cell_emb, conv_lin, cc_idx, cw_idx);
    cudaEventRecord(e_det, 0);

    // side stream: CSR build (needs detect's g_cc64/g_cw64)
    cudaStreamWaitEvent(s_side, e_det, 0);
    zero_all<<<NB_CELL, 256, 0, s_side>>>();
    hist_all<<<NB_EALL, 256, 0, s_side>>>(cc_idx, cw_idx);
    scan1<<<NBLK_SCAN, 1024, 0, s_side>>>();
    scan2p<<<1, 256, 0, s_side>>>(NBLK_SCAN);
    scan3<<<NB_CELL, 256, 0, s_side>>>();
    wscan<<<1, 512, 0, s_side>>>();
    scatter_all<<<NB_EALL, 256, 0, s_side>>>(cc_idx, cw_idx, attr);
    cudaEventRecord(e_csr, s_side);

    // main stream (overlaps with CSR): layer-0 GEMM + well prep
    gemm12<<<N_CELL / 64, 256>>>(cell_x, conv_att_src, conv_att_dst);
    well_prep<<<N_WELL, 64>>>(well_x, W_well_emb, b_well_emb, wc_lin, wc_att_dst);

    // join: edge passes need the CSR
    cudaStreamWaitEvent(0, e_csr, 0);

    edge_fused<<<N_CELL / 8, 256>>>(0);
    for (int l = 1; l < 3; l++) {
        gemm_fused<<<N_CELL / 64, 256>>>(conv_lin + l * H * H,
                                         conv_att_src + l * H,
                                         conv_att_dst + l * H,
                                         conv_bias + (l - 1) * H);
        edge_fused<<<N_CELL / 8, 256>>>(l);
    }

    gemm_fused<<<N_CELL / 64, 256>>>(wc_lin, wc_att_src, wc_att_dst,
                                     conv_bias + 2 * H);
    well_edge_fused<<<N_WELL / 8, 256>>>();
    well_finalize<<<N_WELL, 64>>>(wc_bias, mlp_W1, mlp_b1, mlp_W2, mlp_b2,
                                  (float*)d_out);
}